// round 3
// baseline (speedup 1.0000x reference)
#include <cuda_runtime.h>
#include <cstdint>

// Problem constants
#define B_    16
#define CIN_  256
#define T_    4096
#define N_    64
#define GC_   224
#define EC_   256
#define H_    8
#define HC_   32
#define COUT_ 256

// Scratch (no cudaMalloc allowed)
__device__ float d_g[B_ * N_ * EC_];      // guide embed [b][n][e]
__device__ float d_attn[B_ * H_ * T_];    // sigmoid attention [b][h][t]
__device__ int   d_mask_kind;             // 0=int32, 1=float32, 2=byte(bool)

// ---------------------------------------------------------------------------
// Kernel M: classify mask dtype from its byte pattern (values are 0/1):
//   int32 {0,1}  : nonzero bytes only at idx%4==0
//   float32 {0,1}: nonzero bytes only at idx%4 in {2,3}  (0x3f800000)
//   bool/uint8   : nonzero bytes at all residues
// One block, deterministic.
// ---------------------------------------------------------------------------
__global__ void mask_classify_kernel(const unsigned char* __restrict__ mbytes,
                                     int nbytes)
{
    __shared__ int s_c0, s_c23;
    if (threadIdx.x == 0) { s_c0 = 0; s_c23 = 0; }
    __syncthreads();
    int c0 = 0, c23 = 0;
    for (int i = threadIdx.x; i < nbytes; i += blockDim.x) {
        int r = i & 3;
        if (mbytes[i] != 0) {
            if (r == 0) c0++;
            else if (r >= 2) c23++;
        }
    }
    atomicAdd(&s_c0, c0);
    atomicAdd(&s_c23, c23);
    __syncthreads();
    if (threadIdx.x == 0) {
        int kind;
        if (s_c0 > 0 && s_c23 == 0) kind = 0;       // int32
        else if (s_c0 == 0 && s_c23 > 0) kind = 1;  // float32
        else kind = 2;                              // raw bytes (bool)
        d_mask_kind = kind;
    }
}

// ---------------------------------------------------------------------------
// Kernel A: guide FC   g[b,n,e] = sum_k guide[b,n,k]*gw[e,k] + gb[e]
// ---------------------------------------------------------------------------
__global__ __launch_bounds__(256) void guide_fc_kernel(
    const float* __restrict__ guide, const float* __restrict__ gw,
    const float* __restrict__ gb)
{
    const int b  = blockIdx.y;
    const int n0 = blockIdx.x * 8;
    const int e  = threadIdx.x;

    __shared__ float s_guide[8 * GC_];
    __shared__ float s_gw[256 * 33];

    for (int i = threadIdx.x; i < 8 * GC_; i += 256) {
        int nn = i / GC_, k = i % GC_;
        s_guide[i] = guide[((size_t)(b * N_ + n0 + nn)) * GC_ + k];
    }

    float acc[8];
#pragma unroll
    for (int nn = 0; nn < 8; nn++) acc[nn] = 0.f;

    for (int k0 = 0; k0 < GC_; k0 += 32) {
        __syncthreads();
        for (int i = threadIdx.x; i < 256 * 32; i += 256) {
            int ee = i >> 5, j = i & 31;
            s_gw[ee * 33 + j] = gw[ee * GC_ + k0 + j];
        }
        __syncthreads();
#pragma unroll
        for (int j = 0; j < 32; j++) {
            float w = s_gw[e * 33 + j];
#pragma unroll
            for (int nn = 0; nn < 8; nn++)
                acc[nn] += s_guide[nn * GC_ + k0 + j] * w;
        }
    }

    float bias = gb[e];
#pragma unroll
    for (int nn = 0; nn < 8; nn++)
        d_g[((size_t)(b * N_ + n0 + nn)) * EC_ + e] = acc[nn] + bias;
}

// ---------------------------------------------------------------------------
// Kernel B: attention  attn[b,h,t] = sigmoid( max_n(x . g)/sqrt(32) + bias[h] )
// ---------------------------------------------------------------------------
__global__ __launch_bounds__(256) void attn_kernel(
    const float* __restrict__ x, const float* __restrict__ abias)
{
    const int bh = blockIdx.y;
    const int b = bh >> 3, h = bh & 7;
    const int t = blockIdx.x * 256 + threadIdx.x;

    __shared__ float s_g[N_ * HC_];

    for (int i = threadIdx.x; i < N_ * HC_; i += 256) {
        int n = i >> 5, c = i & 31;
        s_g[i] = d_g[((size_t)(b * N_ + n)) * EC_ + h * HC_ + c];
    }
    __syncthreads();

    float xv[HC_];
    const float* xb = x + ((size_t)b * CIN_ + h * HC_) * T_ + t;
#pragma unroll
    for (int c = 0; c < HC_; c++) xv[c] = xb[(size_t)c * T_];

    float m = -1e30f;
    const float4* g4 = (const float4*)s_g;
#pragma unroll 2
    for (int n = 0; n < N_; n++) {
        float d = 0.f;
#pragma unroll
        for (int q = 0; q < 8; q++) {
            float4 gg = g4[n * 8 + q];
            d += xv[4 * q + 0] * gg.x;
            d += xv[4 * q + 1] * gg.y;
            d += xv[4 * q + 2] * gg.z;
            d += xv[4 * q + 3] * gg.w;
        }
        m = fmaxf(m, d);
    }

    float z = m * 0.17677669529663687f + abias[h];
    d_attn[((size_t)(b * H_ + h)) * T_ + t] = 1.f / (1.f + __expf(-z));
}

// ---------------------------------------------------------------------------
// Mask read helper: returns 1.f / 0.f for logical position t in batch b,
// honoring the detected storage dtype.
// ---------------------------------------------------------------------------
__device__ __forceinline__ float mask_at(const void* mp, int kind, int b, int t)
{
    size_t idx = (size_t)b * T_ + t;
    if (kind == 0)      return ((const int*)mp)[idx]   != 0   ? 1.f : 0.f;
    else if (kind == 1) return ((const float*)mp)[idx] != 0.f ? 1.f : 0.f;
    else                return ((const unsigned char*)mp)[idx] ? 1.f : 0.f;
}

// ---------------------------------------------------------------------------
// Kernel C: conv1d k=3 pad=1 + bias, * mask, * attn[head]
// ---------------------------------------------------------------------------
#define TB_  128
#define CIC_ 16
__global__ __launch_bounds__(256) void conv_kernel(
    const float* __restrict__ x, const float* __restrict__ pw,
    const float* __restrict__ pb, const void* __restrict__ mask,
    float* __restrict__ out)
{
    const int b   = blockIdx.z;
    const int co0 = blockIdx.y * 64;
    const int t0  = blockIdx.x * TB_;
    const int tid = threadIdx.x;
    const int tco = tid >> 4;
    const int tt  = tid & 15;
    const int tl  = tt * 4;

    __shared__ float s_x[CIC_][TB_];
    __shared__ float s_hl[CIC_];
    __shared__ float s_hr[CIC_];
    __shared__ float s_w[64][CIC_ * 3];

    float acc[4][8];
#pragma unroll
    for (int i = 0; i < 4; i++)
#pragma unroll
        for (int j = 0; j < 8; j++) acc[i][j] = 0.f;

    const float* xb = x + (size_t)b * CIN_ * T_;

    for (int ci0 = 0; ci0 < CIN_; ci0 += CIC_) {
        __syncthreads();
        for (int i = tid; i < CIC_ * TB_; i += 256) {
            int ci = i >> 7, t = i & 127;
            s_x[ci][t] = xb[(size_t)(ci0 + ci) * T_ + t0 + t];
        }
        if (tid < CIC_) {
            int ci = tid;
            s_hl[ci] = (t0 > 0)        ? xb[(size_t)(ci0 + ci) * T_ + t0 - 1]   : 0.f;
            s_hr[ci] = (t0 + TB_ < T_) ? xb[(size_t)(ci0 + ci) * T_ + t0 + TB_] : 0.f;
        }
        for (int i = tid; i < 64 * CIC_ * 3; i += 256) {
            int co = i / (CIC_ * 3), r = i % (CIC_ * 3);
            s_w[co][r] = pw[(size_t)(co0 + co) * (CIN_ * 3) + ci0 * 3 + r];
        }
        __syncthreads();

#pragma unroll 4
        for (int ci = 0; ci < CIC_; ci++) {
            float xa[6];
            {
                float4 v = *(const float4*)&s_x[ci][tl];
                xa[1] = v.x; xa[2] = v.y; xa[3] = v.z; xa[4] = v.w;
                xa[0] = (tl > 0) ? s_x[ci][tl - 1] : s_hl[ci];
                xa[5] = s_x[ci][tl + 4];
            }
            float xc[6];
            {
                float4 v = *(const float4*)&s_x[ci][64 + tl];
                xc[1] = v.x; xc[2] = v.y; xc[3] = v.z; xc[4] = v.w;
                xc[0] = s_x[ci][64 + tl - 1];
                xc[5] = (64 + tl + 4 < TB_) ? s_x[ci][64 + tl + 4] : s_hr[ci];
            }
#pragma unroll
            for (int i = 0; i < 4; i++) {
                float w0 = s_w[tco * 4 + i][ci * 3 + 0];
                float w1 = s_w[tco * 4 + i][ci * 3 + 1];
                float w2 = s_w[tco * 4 + i][ci * 3 + 2];
#pragma unroll
                for (int j = 0; j < 4; j++) {
                    acc[i][j]     += w0 * xa[j] + w1 * xa[j + 1] + w2 * xa[j + 2];
                    acc[i][j + 4] += w0 * xc[j] + w1 * xc[j + 1] + w2 * xc[j + 2];
                }
            }
        }
    }

    // ---- epilogue ----
    const int mk = d_mask_kind;
    float mA[4], mB[4];
#pragma unroll
    for (int j = 0; j < 4; j++) {
        mA[j] = mask_at(mask, mk, b, t0 + tl + j);
        mB[j] = mask_at(mask, mk, b, t0 + 64 + tl + j);
    }

#pragma unroll
    for (int i = 0; i < 4; i++) {
        int co = co0 + tco * 4 + i;
        int h  = co >> 5;
        float bias = __ldg(&pb[co]);
        const float* arow = d_attn + ((size_t)(b * H_ + h)) * T_ + t0 + tl;
        float4 aA = *(const float4*)(arow);
        float4 aB = *(const float4*)(arow + 64);
        float* orow = out + ((size_t)(b * COUT_ + co)) * T_ + t0 + tl;

        float4 oA, oB;
        oA.x = (acc[i][0] + bias) * aA.x * mA[0];
        oA.y = (acc[i][1] + bias) * aA.y * mA[1];
        oA.z = (acc[i][2] + bias) * aA.z * mA[2];
        oA.w = (acc[i][3] + bias) * aA.w * mA[3];
        oB.x = (acc[i][4] + bias) * aB.x * mB[0];
        oB.y = (acc[i][5] + bias) * aB.y * mB[1];
        oB.z = (acc[i][6] + bias) * aB.z * mB[2];
        oB.w = (acc[i][7] + bias) * aB.w * mB[3];
        *(float4*)(orow)      = oA;
        *(float4*)(orow + 64) = oB;
    }
}

// ---------------------------------------------------------------------------
extern "C" void kernel_launch(void* const* d_in, const int* in_sizes, int n_in,
                              void* d_out, int out_size)
{
    const float* x     = (const float*)d_in[0];
    const float* guide = (const float*)d_in[1];
    const void*  mask  = (const void*)d_in[2];
    const float* gw    = (const float*)d_in[3];
    const float* gb    = (const float*)d_in[4];
    const float* abias = (const float*)d_in[5];
    const float* pw    = (const float*)d_in[6];
    const float* pb    = (const float*)d_in[7];
    float*       out   = (float*)d_out;

    // Classify mask dtype from raw bytes. in_sizes[2] is the element count;
    // scanning that many BYTES is a safe lower bound for any dtype >= 1 byte,
    // and with B*T = 65536 elements the residue statistics are unambiguous.
    mask_classify_kernel<<<1, 256>>>((const unsigned char*)mask, in_sizes[2]);
    guide_fc_kernel<<<dim3(N_ / 8, B_), 256>>>(guide, gw, gb);
    attn_kernel<<<dim3(T_ / 256, B_ * H_), 256>>>(x, abias);
    conv_kernel<<<dim3(T_ / TB_, COUT_ / 64, B_), 256>>>(x, pw, pb, mask, out);
}

// round 8
// speedup vs baseline: 2.5396x; 2.5396x over previous
#include <cuda_runtime.h>
#include <cstdint>

// Problem constants
#define B_    16
#define CIN_  256
#define T_    4096
#define N_    64
#define GC_   224
#define EC_   256
#define H_    8
#define HC_   32
#define COUT_ 256

// Scratch (no cudaMalloc allowed)
__device__ float d_g[B_ * N_ * EC_];            // guide embed [b][n][e]
__device__ float d_attn[B_ * H_ * T_];          // sigmoid attention [b][h][t]
__device__ float d_xt[(size_t)B_ * T_ * CIN_];  // x transposed [b][t][ci] (64 MB)
__device__ float d_wfrag[3 * 16 * 32 * 128];    // A-fragments for conv
__device__ float d_gfrag[16 * 8 * 16 * 128];    // A-fragments for attn
__device__ int   d_mask_kind;                   // 0=int32, 1=float32, 2=byte(bool)

// ---------------------------------------------------------------------------
// Helpers (base sm_100-legal: mma.sync sm_80+, ldmatrix sm_75+)
// ---------------------------------------------------------------------------
__device__ __forceinline__ uint32_t smem_u32(const void* p) {
    uint32_t a;
    asm("{ .reg .u64 t; cvta.to.shared.u64 t, %1; cvt.u32.u64 %0, t; }"
        : "=r"(a) : "l"(p));
    return a;
}
__device__ __forceinline__ float tf32_rna(float f) {
    uint32_t u;
    asm("cvt.rna.tf32.f32 %0, %1;" : "=r"(u) : "f"(f));
    return __uint_as_float(u);
}
__device__ __forceinline__ float4 tf32_rna4(float4 v) {
    v.x = tf32_rna(v.x); v.y = tf32_rna(v.y);
    v.z = tf32_rna(v.z); v.w = tf32_rna(v.w);
    return v;
}
__device__ __forceinline__ void ldsm_x2(uint32_t* r, uint32_t addr) {
    asm volatile("ldmatrix.sync.aligned.m8n8.x2.shared.b16 {%0, %1}, [%2];"
                 : "=r"(r[0]), "=r"(r[1]) : "r"(addr));
}
__device__ __forceinline__ void mma_tf32(float* d, const uint32_t* a, const uint32_t* b) {
    asm volatile(
        "mma.sync.aligned.m16n8k8.row.col.f32.tf32.tf32.f32 "
        "{%0,%1,%2,%3}, {%4,%5,%6,%7}, {%8,%9}, {%0,%1,%2,%3};"
        : "+f"(d[0]), "+f"(d[1]), "+f"(d[2]), "+f"(d[3])
        : "r"(a[0]), "r"(a[1]), "r"(a[2]), "r"(a[3]), "r"(b[0]), "r"(b[1]));
}
// Swizzled tile: row r (32 floats = 8 groups of 16B), logical group g stored at
// physical group g ^ (r&7). Returns BYTE offset within tile.
__device__ __forceinline__ uint32_t swz(int r, int g) {
    return (uint32_t)((r * 8 + (g ^ (r & 7))) << 4);
}

// ---------------------------------------------------------------------------
// Kernel M: classify mask dtype (proven R3)
// ---------------------------------------------------------------------------
__global__ void mask_classify_kernel(const unsigned char* __restrict__ mbytes,
                                     int nbytes)
{
    __shared__ int s_c0, s_c23;
    if (threadIdx.x == 0) { s_c0 = 0; s_c23 = 0; }
    __syncthreads();
    int c0 = 0, c23 = 0;
    for (int i = threadIdx.x; i < nbytes; i += blockDim.x) {
        int r = i & 3;
        if (mbytes[i] != 0) {
            if (r == 0) c0++;
            else if (r >= 2) c23++;
        }
    }
    atomicAdd(&s_c0, c0);
    atomicAdd(&s_c23, c23);
    __syncthreads();
    if (threadIdx.x == 0) {
        int kind;
        if (s_c0 > 0 && s_c23 == 0) kind = 0;
        else if (s_c0 == 0 && s_c23 > 0) kind = 1;
        else kind = 2;
        d_mask_kind = kind;
    }
}

__device__ __forceinline__ float mask_at(const void* mp, int kind, int b, int t)
{
    size_t idx = (size_t)b * T_ + t;
    if (kind == 0)      return ((const int*)mp)[idx]   != 0   ? 1.f : 0.f;
    else if (kind == 1) return ((const float*)mp)[idx] != 0.f ? 1.f : 0.f;
    else                return ((const unsigned char*)mp)[idx] ? 1.f : 0.f;
}

// ---------------------------------------------------------------------------
// Kernel A: guide FC (proven R3)
// ---------------------------------------------------------------------------
__global__ __launch_bounds__(256) void guide_fc_kernel(
    const float* __restrict__ guide, const float* __restrict__ gw,
    const float* __restrict__ gb)
{
    const int b  = blockIdx.y;
    const int n0 = blockIdx.x * 8;
    const int e  = threadIdx.x;

    __shared__ float s_guide[8 * GC_];
    __shared__ float s_gw[256 * 33];

    for (int i = threadIdx.x; i < 8 * GC_; i += 256) {
        int nn = i / GC_, k = i % GC_;
        s_guide[i] = guide[((size_t)(b * N_ + n0 + nn)) * GC_ + k];
    }

    float acc[8];
#pragma unroll
    for (int nn = 0; nn < 8; nn++) acc[nn] = 0.f;

    for (int k0 = 0; k0 < GC_; k0 += 32) {
        __syncthreads();
        for (int i = threadIdx.x; i < 256 * 32; i += 256) {
            int ee = i >> 5, j = i & 31;
            s_gw[ee * 33 + j] = gw[ee * GC_ + k0 + j];
        }
        __syncthreads();
#pragma unroll
        for (int j = 0; j < 32; j++) {
            float w = s_gw[e * 33 + j];
#pragma unroll
            for (int nn = 0; nn < 8; nn++)
                acc[nn] += s_guide[nn * GC_ + k0 + j] * w;
        }
    }

    float bias = gb[e];
#pragma unroll
    for (int nn = 0; nn < 8; nn++)
        d_g[((size_t)(b * N_ + n0 + nn)) * EC_ + e] = acc[nn] + bias;
}

// ---------------------------------------------------------------------------
// Kernel X: transpose x[b][ci][t] -> d_xt[b][t][ci] (proven layout, R4)
// ---------------------------------------------------------------------------
__global__ void xt_kernel(const float* __restrict__ x)
{
    __shared__ float s[32][33];
    const int b = blockIdx.z, ci0 = blockIdx.y * 32, t0 = blockIdx.x * 32;
    const int tx = threadIdx.x, ty = threadIdx.y;
#pragma unroll
    for (int k = 0; k < 4; k++)
        s[ty + 8 * k][tx] = x[((size_t)(b * CIN_ + ci0 + ty + 8 * k)) * T_ + t0 + tx];
    __syncthreads();
#pragma unroll
    for (int k = 0; k < 4; k++)
        d_xt[((size_t)b * T_ + t0 + ty + 8 * k) * CIN_ + ci0 + tx] = s[tx][ty + 8 * k];
}

// ---------------------------------------------------------------------------
// Kernel W: pack conv weights into per-lane A-fragments (tf32-rounded).
// a0=(co,ci) a1=(co+8,ci) a2=(co,ci+4) a3=(co+8,ci+4); pw is [co][ci][k].
// ---------------------------------------------------------------------------
__global__ __launch_bounds__(256) void wfrag_kernel(const float* __restrict__ pw)
{
    const int cog = blockIdx.x, tap = blockIdx.y;
    for (int i = threadIdx.x; i < 1024; i += 256) {
        int cic = i >> 5, lane = i & 31;
        int co = cog * 16 + (lane >> 2);
        int ci = cic * 8 + (lane & 3);
        float4 v;
        v.x = tf32_rna(pw[(size_t)(co * 256 + ci) * 3 + tap]);
        v.y = tf32_rna(pw[(size_t)((co + 8) * 256 + ci) * 3 + tap]);
        v.z = tf32_rna(pw[(size_t)(co * 256 + ci + 4) * 3 + tap]);
        v.w = tf32_rna(pw[(size_t)((co + 8) * 256 + ci + 4) * 3 + tap]);
        *(float4*)&d_wfrag[((size_t)(tap * 16 + cog) * 32 + cic) * 128 + lane * 4] = v;
    }
}

// ---------------------------------------------------------------------------
// Kernel G: pack guide embeds into per-lane A-fragments per (b, h).
// ---------------------------------------------------------------------------
__global__ __launch_bounds__(256) void gfrag_kernel()
{
    const int b = blockIdx.x;
    const float* gb = d_g + (size_t)b * N_ * EC_;
    for (int i = threadIdx.x; i < 4096; i += 256) {
        int h = i >> 9, mg = (i >> 7) & 3, kc = (i >> 5) & 3, lane = i & 31;
        int n = mg * 16 + (lane >> 2);
        int e = h * 32 + kc * 8 + (lane & 3);
        float4 v;
        v.x = tf32_rna(gb[(size_t)n * 256 + e]);
        v.y = tf32_rna(gb[(size_t)(n + 8) * 256 + e]);
        v.z = tf32_rna(gb[(size_t)n * 256 + e + 4]);
        v.w = tf32_rna(gb[(size_t)(n + 8) * 256 + e + 4]);
        *(float4*)&d_gfrag[((size_t)(b * 8 + h) * 16 + mg * 4 + kc) * 128 + lane * 4] = v;
    }
}

// ---------------------------------------------------------------------------
// Kernel B: attention via mma.sync tf32.
// CTA = (t-tile 256, b). Buffer: 256 rows x 32 c (one head), swizzled,
// double-buffered across heads. D[n][t] = sum_c g[n][c] x[c][t]; max; sigmoid.
// ---------------------------------------------------------------------------
#define ATTN_TILE_B 32768   // 256 rows * 128B

__device__ __forceinline__ void attn_stage(const float* __restrict__ xtb,
                                           char* buf, int h, int t0, int tid)
{
#pragma unroll
    for (int it = 0; it < 8; it++) {
        int idx = tid + it * 256;          // 2048 float4
        int r = idx >> 3, g = idx & 7;
        float4 v = *(const float4*)(xtb + (size_t)(t0 + r) * 256 + h * 32 + g * 4);
        *(float4*)(buf + swz(r, g)) = tf32_rna4(v);
    }
}

__global__ __launch_bounds__(256, 2) void attn_mma_kernel(const float* __restrict__ abias)
{
    extern __shared__ __align__(16) char s_dyn[];
    const int b = blockIdx.y, t0 = blockIdx.x * 256;
    const int tid = threadIdx.x, w = tid >> 5, lane = tid & 31;
    const uint32_t smb = smem_u32(s_dyn);
    const float* xtb = d_xt + (size_t)b * T_ * CIN_;

    attn_stage(xtb, s_dyn, 0, t0, tid);

    for (int h = 0; h < 8; h++) {
        __syncthreads();
        if (h < 7) attn_stage(xtb, s_dyn + ((h + 1) & 1) * ATTN_TILE_B, h + 1, t0, tid);
        const uint32_t bufb = smb + (h & 1) * ATTN_TILE_B;

        float acc[4][4][4];
#pragma unroll
        for (int mg = 0; mg < 4; mg++)
#pragma unroll
            for (int nt = 0; nt < 4; nt++)
#pragma unroll
                for (int r = 0; r < 4; r++) acc[mg][nt][r] = 0.f;

#pragma unroll
        for (int kc = 0; kc < 4; kc++) {
            uint32_t afr[4][4];
#pragma unroll
            for (int mg = 0; mg < 4; mg++) {
                float4 v = *(const float4*)&d_gfrag[((size_t)(b * 8 + h) * 16 + mg * 4 + kc) * 128 + lane * 4];
                afr[mg][0] = __float_as_uint(v.x); afr[mg][1] = __float_as_uint(v.y);
                afr[mg][2] = __float_as_uint(v.z); afr[mg][3] = __float_as_uint(v.w);
            }
            const int gk = kc * 2 + ((lane >> 3) & 1);
#pragma unroll
            for (int nt = 0; nt < 4; nt++) {
                const int r = w * 32 + nt * 8 + (lane & 7);
                uint32_t bfr[2];
                ldsm_x2(bfr, bufb + swz(r, gk));
#pragma unroll
                for (int mg = 0; mg < 4; mg++)
                    mma_tf32(acc[mg][nt], afr[mg], bfr);
            }
        }

        const float ab = abias[h];
        float* orow = d_attn + ((size_t)(b * 8 + h)) * T_;
#pragma unroll
        for (int nt = 0; nt < 4; nt++) {
            float m0 = -1e30f, m1 = -1e30f;
#pragma unroll
            for (int mg = 0; mg < 4; mg++) {
                m0 = fmaxf(m0, fmaxf(acc[mg][nt][0], acc[mg][nt][2]));
                m1 = fmaxf(m1, fmaxf(acc[mg][nt][1], acc[mg][nt][3]));
            }
#pragma unroll
            for (int d = 4; d <= 16; d <<= 1) {
                m0 = fmaxf(m0, __shfl_xor_sync(0xffffffffu, m0, d));
                m1 = fmaxf(m1, __shfl_xor_sync(0xffffffffu, m1, d));
            }
            if (lane < 4) {
                int t = t0 + w * 32 + nt * 8 + 2 * lane;
                float z0 = m0 * 0.17677669529663687f + ab;
                float z1 = m1 * 0.17677669529663687f + ab;
                float2 o;
                o.x = 1.f / (1.f + __expf(-z0));
                o.y = 1.f / (1.f + __expf(-z1));
                *(float2*)(orow + t) = o;
            }
        }
    }
}

// ---------------------------------------------------------------------------
// Kernel C: conv1d k=3 as 3-tap implicit GEMM via mma.sync tf32.
// CTA = 64 co x 256 t. Buffer: 258 rows (t0-1 .. t0+256) x 32 ci, swizzled,
// double-buffered across 8 ci-chunks. Warp w: cog=(w&1)*32 co, tg=(w>>1)*64 t.
// ---------------------------------------------------------------------------
#define CONV_TILE_B 33024   // 258 rows * 128B

__device__ __forceinline__ void conv_stage(const float* __restrict__ xtb,
                                           char* buf, int sc, int t0, int tid)
{
#pragma unroll
    for (int it = 0; it < 9; it++) {
        int idx = tid + it * 256;          // 2064 float4
        if (it < 8 || idx < 2064) {
            int r = idx >> 3, g = idx & 7;
            int gt = t0 - 1 + r;
            float4 v;
            if (gt >= 0 && gt < T_)
                v = tf32_rna4(*(const float4*)(xtb + (size_t)gt * 256 + sc * 32 + g * 4));
            else
                v = make_float4(0.f, 0.f, 0.f, 0.f);
            *(float4*)(buf + swz(r, g)) = v;
        }
    }
}

__global__ __launch_bounds__(256, 2) void conv_mma_kernel(
    const float* __restrict__ pb, const void* __restrict__ mask,
    float* __restrict__ out)
{
    extern __shared__ __align__(16) char s_dyn[];
    const int b = blockIdx.z, co0 = blockIdx.y * 64, t0 = blockIdx.x * 256;
    const int tid = threadIdx.x, w = tid >> 5, lane = tid & 31;
    const int cog = w & 1, tg = w >> 1;
    const uint32_t smb = smem_u32(s_dyn);
    const float* xtb = d_xt + (size_t)b * T_ * CIN_;

    float acc[2][8][4];
#pragma unroll
    for (int mf = 0; mf < 2; mf++)
#pragma unroll
        for (int nt = 0; nt < 8; nt++)
#pragma unroll
            for (int r = 0; r < 4; r++) acc[mf][nt][r] = 0.f;

    conv_stage(xtb, s_dyn, 0, t0, tid);

    for (int sc = 0; sc < 8; sc++) {
        __syncthreads();
        if (sc < 7) conv_stage(xtb, s_dyn + ((sc + 1) & 1) * CONV_TILE_B, sc + 1, t0, tid);
        const uint32_t bufb = smb + (sc & 1) * CONV_TILE_B;

#pragma unroll
        for (int kc = 0; kc < 4; kc++) {
            const int cic = sc * 4 + kc;
            uint32_t afr[2][3][4];
#pragma unroll
            for (int mf = 0; mf < 2; mf++) {
                const int cog16 = blockIdx.y * 4 + cog * 2 + mf;
#pragma unroll
                for (int tap = 0; tap < 3; tap++) {
                    float4 v = *(const float4*)&d_wfrag[((size_t)(tap * 16 + cog16) * 32 + cic) * 128 + lane * 4];
                    afr[mf][tap][0] = __float_as_uint(v.x);
                    afr[mf][tap][1] = __float_as_uint(v.y);
                    afr[mf][tap][2] = __float_as_uint(v.z);
                    afr[mf][tap][3] = __float_as_uint(v.w);
                }
            }
            const int gk = kc * 2 + ((lane >> 3) & 1);
#pragma unroll
            for (int nt = 0; nt < 8; nt++) {
                uint32_t bfr[3][2];
#pragma unroll
                for (int s = 0; s < 3; s++) {
                    const int r = tg * 64 + nt * 8 + s + (lane & 7);
                    ldsm_x2(bfr[s], bufb + swz(r, gk));
                }
#pragma unroll
                for (int mf = 0; mf < 2; mf++)
#pragma unroll
                    for (int tap = 0; tap < 3; tap++)
                        mma_tf32(acc[mf][nt], afr[mf][tap], bfr[tap]);
            }
        }
    }

    // ---- epilogue ----
    const int mk = d_mask_kind;
    const int h = (co0 + cog * 32) >> 5;
    const float* arow = d_attn + ((size_t)(b * 8 + h)) * T_;
#pragma unroll
    for (int mf = 0; mf < 2; mf++) {
        const int cob = co0 + cog * 32 + mf * 16 + (lane >> 2);
        const float bias0 = pb[cob], bias1 = pb[cob + 8];
        float* o0 = out + ((size_t)(b * 256 + cob)) * T_;
        float* o1 = o0 + (size_t)8 * T_;
#pragma unroll
        for (int nt = 0; nt < 8; nt++) {
            const int t = t0 + tg * 64 + nt * 8 + 2 * (lane & 3);
            float2 a = *(const float2*)(arow + t);
            float m0 = mask_at(mask, mk, b, t);
            float m1 = mask_at(mask, mk, b, t + 1);
            float2 v0, v1;
            v0.x = (acc[mf][nt][0] + bias0) * a.x * m0;
            v0.y = (acc[mf][nt][1] + bias0) * a.y * m1;
            v1.x = (acc[mf][nt][2] + bias1) * a.x * m0;
            v1.y = (acc[mf][nt][3] + bias1) * a.y * m1;
            *(float2*)(o0 + t) = v0;
            *(float2*)(o1 + t) = v1;
        }
    }
}

// ---------------------------------------------------------------------------
extern "C" void kernel_launch(void* const* d_in, const int* in_sizes, int n_in,
                              void* d_out, int out_size)
{
    const float* x     = (const float*)d_in[0];
    const float* guide = (const float*)d_in[1];
    const void*  mask  = (const void*)d_in[2];
    const float* gw    = (const float*)d_in[3];
    const float* gb    = (const float*)d_in[4];
    const float* abias = (const float*)d_in[5];
    const float* pw    = (const float*)d_in[6];
    const float* pb    = (const float*)d_in[7];
    float*       out   = (float*)d_out;

    static int attr_done = 0;
    if (!attr_done) {
        cudaFuncSetAttribute(attn_mma_kernel,
                             cudaFuncAttributeMaxDynamicSharedMemorySize, ATTN_TILE_B * 2);
        cudaFuncSetAttribute(conv_mma_kernel,
                             cudaFuncAttributeMaxDynamicSharedMemorySize, CONV_TILE_B * 2);
        attr_done = 1;
    }

    mask_classify_kernel<<<1, 256>>>((const unsigned char*)mask, in_sizes[2]);
    guide_fc_kernel<<<dim3(N_ / 8, B_), 256>>>(guide, gw, gb);
    wfrag_kernel<<<dim3(16, 3), 256>>>(pw);
    gfrag_kernel<<<16, 256>>>();
    xt_kernel<<<dim3(T_ / 32, CIN_ / 32, B_), dim3(32, 8)>>>(x);
    attn_mma_kernel<<<dim3(T_ / 256, B_), 256, ATTN_TILE_B * 2>>>(abias);
    conv_mma_kernel<<<dim3(T_ / 256, COUT_ / 64, B_), 256, CONV_TILE_B * 2>>>(pb, mask, out);
}

// round 9
// speedup vs baseline: 3.1580x; 1.2435x over previous
#include <cuda_runtime.h>
#include <cstdint>

// Problem constants
#define B_    16
#define CIN_  256
#define T_    4096
#define N_    64
#define GC_   224
#define EC_   256
#define H_    8
#define HC_   32
#define COUT_ 256

// Scratch (no cudaMalloc allowed)
__device__ float d_g[B_ * N_ * EC_];            // guide embed [b][n][e]
__device__ float d_xt[(size_t)B_ * T_ * CIN_];  // x transposed [b][t][ci] (64 MB)
__device__ float d_wfrag[3 * 16 * 32 * 128];    // A-fragments for conv
__device__ float d_gfrag[16 * 8 * 16 * 128];    // A-fragments for attn
__device__ int   d_mask_kind;                   // 0=int32, 1=float32, 2=byte(bool)

// ---------------------------------------------------------------------------
// Helpers (base sm_100-legal: mma.sync sm_80+, ldmatrix sm_75+)
// ---------------------------------------------------------------------------
__device__ __forceinline__ uint32_t smem_u32(const void* p) {
    uint32_t a;
    asm("{ .reg .u64 t; cvta.to.shared.u64 t, %1; cvt.u32.u64 %0, t; }"
        : "=r"(a) : "l"(p));
    return a;
}
__device__ __forceinline__ float tf32_rna(float f) {
    uint32_t u;
    asm("cvt.rna.tf32.f32 %0, %1;" : "=r"(u) : "f"(f));
    return __uint_as_float(u);
}
__device__ __forceinline__ float4 tf32_rna4(float4 v) {
    v.x = tf32_rna(v.x); v.y = tf32_rna(v.y);
    v.z = tf32_rna(v.z); v.w = tf32_rna(v.w);
    return v;
}
__device__ __forceinline__ void ldsm_x2(uint32_t* r, uint32_t addr) {
    asm volatile("ldmatrix.sync.aligned.m8n8.x2.shared.b16 {%0, %1}, [%2];"
                 : "=r"(r[0]), "=r"(r[1]) : "r"(addr));
}
__device__ __forceinline__ void mma_tf32(float* d, const uint32_t* a, const uint32_t* b) {
    asm volatile(
        "mma.sync.aligned.m16n8k8.row.col.f32.tf32.tf32.f32 "
        "{%0,%1,%2,%3}, {%4,%5,%6,%7}, {%8,%9}, {%0,%1,%2,%3};"
        : "+f"(d[0]), "+f"(d[1]), "+f"(d[2]), "+f"(d[3])
        : "r"(a[0]), "r"(a[1]), "r"(a[2]), "r"(a[3]), "r"(b[0]), "r"(b[1]));
}
// Swizzled tile: row r (32 floats = 8 groups of 16B), logical group g stored at
// physical group g ^ (r&7). Returns BYTE offset within tile.
__device__ __forceinline__ uint32_t swz(int r, int g) {
    return (uint32_t)((r * 8 + (g ^ (r & 7))) << 4);
}

// ---------------------------------------------------------------------------
// Kernel M: classify mask dtype (proven R3; vectorized uint4)
// ---------------------------------------------------------------------------
__global__ void mask_classify_kernel(const uint4* __restrict__ m16, int n16)
{
    __shared__ int s_c0, s_c23;
    if (threadIdx.x == 0) { s_c0 = 0; s_c23 = 0; }
    __syncthreads();
    int c0 = 0, c23 = 0;
    for (int i = threadIdx.x; i < n16; i += blockDim.x) {
        uint4 v = m16[i];
        uint32_t ws[4] = { v.x, v.y, v.z, v.w };
#pragma unroll
        for (int k = 0; k < 4; k++) {
            if (ws[k] & 0x000000FFu) c0++;
            if (ws[k] & 0xFFFF0000u) c23++;
        }
    }
    atomicAdd(&s_c0, c0);
    atomicAdd(&s_c23, c23);
    __syncthreads();
    if (threadIdx.x == 0) {
        int kind;
        if (s_c0 > 0 && s_c23 == 0) kind = 0;
        else if (s_c0 == 0 && s_c23 > 0) kind = 1;
        else kind = 2;
        d_mask_kind = kind;
    }
}

__device__ __forceinline__ float mask_at(const void* mp, int kind, int b, int t)
{
    size_t idx = (size_t)b * T_ + t;
    if (kind == 0)      return ((const int*)mp)[idx]   != 0   ? 1.f : 0.f;
    else if (kind == 1) return ((const float*)mp)[idx] != 0.f ? 1.f : 0.f;
    else                return ((const unsigned char*)mp)[idx] ? 1.f : 0.f;
}

// ---------------------------------------------------------------------------
// Kernel A: guide FC (proven R3)
// ---------------------------------------------------------------------------
__global__ __launch_bounds__(256) void guide_fc_kernel(
    const float* __restrict__ guide, const float* __restrict__ gw,
    const float* __restrict__ gb)
{
    const int b  = blockIdx.y;
    const int n0 = blockIdx.x * 8;
    const int e  = threadIdx.x;

    __shared__ float s_guide[8 * GC_];
    __shared__ float s_gw[256 * 33];

    for (int i = threadIdx.x; i < 8 * GC_; i += 256) {
        int nn = i / GC_, k = i % GC_;
        s_guide[i] = guide[((size_t)(b * N_ + n0 + nn)) * GC_ + k];
    }

    float acc[8];
#pragma unroll
    for (int nn = 0; nn < 8; nn++) acc[nn] = 0.f;

    for (int k0 = 0; k0 < GC_; k0 += 32) {
        __syncthreads();
        for (int i = threadIdx.x; i < 256 * 32; i += 256) {
            int ee = i >> 5, j = i & 31;
            s_gw[ee * 33 + j] = gw[ee * GC_ + k0 + j];
        }
        __syncthreads();
#pragma unroll
        for (int j = 0; j < 32; j++) {
            float w = s_gw[e * 33 + j];
#pragma unroll
            for (int nn = 0; nn < 8; nn++)
                acc[nn] += s_guide[nn * GC_ + k0 + j] * w;
        }
    }

    float bias = gb[e];
#pragma unroll
    for (int nn = 0; nn < 8; nn++)
        d_g[((size_t)(b * N_ + n0 + nn)) * EC_ + e] = acc[nn] + bias;
}

// ---------------------------------------------------------------------------
// Kernel X: transpose x[b][ci][t] -> d_xt[b][t][ci] (proven R8)
// ---------------------------------------------------------------------------
__global__ void xt_kernel(const float* __restrict__ x)
{
    __shared__ float s[32][33];
    const int b = blockIdx.z, ci0 = blockIdx.y * 32, t0 = blockIdx.x * 32;
    const int tx = threadIdx.x, ty = threadIdx.y;
#pragma unroll
    for (int k = 0; k < 4; k++)
        s[ty + 8 * k][tx] = x[((size_t)(b * CIN_ + ci0 + ty + 8 * k)) * T_ + t0 + tx];
    __syncthreads();
#pragma unroll
    for (int k = 0; k < 4; k++)
        d_xt[((size_t)b * T_ + t0 + ty + 8 * k) * CIN_ + ci0 + tx] = s[tx][ty + 8 * k];
}

// ---------------------------------------------------------------------------
// Kernel W: pack conv weights into per-lane A-fragments (proven R8)
// ---------------------------------------------------------------------------
__global__ __launch_bounds__(256) void wfrag_kernel(const float* __restrict__ pw)
{
    const int cog = blockIdx.x, tap = blockIdx.y;
    for (int i = threadIdx.x; i < 1024; i += 256) {
        int cic = i >> 5, lane = i & 31;
        int co = cog * 16 + (lane >> 2);
        int ci = cic * 8 + (lane & 3);
        float4 v;
        v.x = tf32_rna(pw[(size_t)(co * 256 + ci) * 3 + tap]);
        v.y = tf32_rna(pw[(size_t)((co + 8) * 256 + ci) * 3 + tap]);
        v.z = tf32_rna(pw[(size_t)(co * 256 + ci + 4) * 3 + tap]);
        v.w = tf32_rna(pw[(size_t)((co + 8) * 256 + ci + 4) * 3 + tap]);
        *(float4*)&d_wfrag[((size_t)(tap * 16 + cog) * 32 + cic) * 128 + lane * 4] = v;
    }
}

// ---------------------------------------------------------------------------
// Kernel G: pack guide embeds into per-lane A-fragments per (b, h).
// Widened: grid (8 h, 16 b), each block covers mg4 x kc4 x 32 lanes = 512.
// ---------------------------------------------------------------------------
__global__ __launch_bounds__(256) void gfrag_kernel()
{
    const int h = blockIdx.x, b = blockIdx.y;
    const float* gb = d_g + (size_t)b * N_ * EC_;
    for (int i = threadIdx.x; i < 512; i += 256) {
        int mg = (i >> 7) & 3, kc = (i >> 5) & 3, lane = i & 31;
        int n = mg * 16 + (lane >> 2);
        int e = h * 32 + kc * 8 + (lane & 3);
        float4 v;
        v.x = tf32_rna(gb[(size_t)n * 256 + e]);
        v.y = tf32_rna(gb[(size_t)(n + 8) * 256 + e]);
        v.z = tf32_rna(gb[(size_t)n * 256 + e + 4]);
        v.w = tf32_rna(gb[(size_t)(n + 8) * 256 + e + 4]);
        *(float4*)&d_gfrag[((size_t)(b * 8 + h) * 16 + mg * 4 + kc) * 128 + lane * 4] = v;
    }
}

// ---------------------------------------------------------------------------
// Kernel C: fused conv1d(k=3) + max-sigmoid attention, all mma.sync tf32.
// CTA = 128 co x 128 t. Buffer: 130 rows (t0-1 .. t0+128) x 32 ci, swizzled,
// double-buffered over 8 ci-chunks. 8 warps = 4 cog (32 co) x 2 tg (64 t).
// Head for warp = blockIdx.y*4 + cog; its attention is computed from the
// staged chunk sc == head (channels [32h,32h+32)) with gfrag A-fragments,
// reduced max-over-n in-register (shfl butterfly leaves every lane the max
// for its own epilogue columns), sigmoid applied, kept in registers.
// Epilogue: out = (conv + pb) * attn * mask.
// ---------------------------------------------------------------------------
#define CONV_ROWS   130
#define CONV_TILE_B (CONV_ROWS * 128)   // 16640 B

__device__ __forceinline__ void conv_stage(const float* __restrict__ xtb,
                                           char* buf, int sc, int t0, int tid)
{
#pragma unroll
    for (int it = 0; it < 5; it++) {
        int idx = tid + it * 256;           // 1040 float4
        if (it < 4 || idx < 1040) {
            int r = idx >> 3, g = idx & 7;
            int gt = t0 - 1 + r;
            float4 v;
            if (gt >= 0 && gt < T_)
                v = tf32_rna4(*(const float4*)(xtb + (size_t)gt * 256 + sc * 32 + g * 4));
            else
                v = make_float4(0.f, 0.f, 0.f, 0.f);
            *(float4*)(buf + swz(r, g)) = v;
        }
    }
}

__global__ __launch_bounds__(256, 2) void conv_mma_kernel(
    const float* __restrict__ pb, const void* __restrict__ mask,
    const float* __restrict__ abias, float* __restrict__ out)
{
    extern __shared__ __align__(16) char s_dyn[];
    const int b = blockIdx.z, co0 = blockIdx.y * 128, t0 = blockIdx.x * 128;
    const int tid = threadIdx.x, w = tid >> 5, lane = tid & 31;
    const int cog = w & 3, tg = w >> 2;
    const int hw = blockIdx.y * 4 + cog;     // this warp's head (== its sc chunk)
    const uint32_t smb = smem_u32(s_dyn);
    const float* xtb = d_xt + (size_t)b * T_ * CIN_;

    float acc[2][8][4];
#pragma unroll
    for (int mf = 0; mf < 2; mf++)
#pragma unroll
        for (int nt = 0; nt < 8; nt++)
#pragma unroll
            for (int r = 0; r < 4; r++) acc[mf][nt][r] = 0.f;

    float attn0[8], attn1[8];
    const float ab = abias[hw];

    conv_stage(xtb, s_dyn, 0, t0, tid);

    for (int sc = 0; sc < 8; sc++) {
        __syncthreads();
        if (sc < 7) conv_stage(xtb, s_dyn + ((sc + 1) & 1) * CONV_TILE_B, sc + 1, t0, tid);
        const uint32_t bufb = smb + (sc & 1) * CONV_TILE_B;

        // ---- conv MMAs ----
#pragma unroll
        for (int kc = 0; kc < 4; kc++) {
            const int cic = sc * 4 + kc;
            uint32_t afr[2][3][4];
#pragma unroll
            for (int mf = 0; mf < 2; mf++) {
                const int cog16 = blockIdx.y * 8 + cog * 2 + mf;
#pragma unroll
                for (int tap = 0; tap < 3; tap++) {
                    float4 v = *(const float4*)&d_wfrag[((size_t)(tap * 16 + cog16) * 32 + cic) * 128 + lane * 4];
                    afr[mf][tap][0] = __float_as_uint(v.x);
                    afr[mf][tap][1] = __float_as_uint(v.y);
                    afr[mf][tap][2] = __float_as_uint(v.z);
                    afr[mf][tap][3] = __float_as_uint(v.w);
                }
            }
            const int gk = kc * 2 + ((lane >> 3) & 1);
#pragma unroll
            for (int nt = 0; nt < 8; nt++) {
                uint32_t bfr[3][2];
#pragma unroll
                for (int s = 0; s < 3; s++) {
                    const int r = tg * 64 + nt * 8 + s + (lane & 7);
                    ldsm_x2(bfr[s], bufb + swz(r, gk));
                }
#pragma unroll
                for (int mf = 0; mf < 2; mf++)
#pragma unroll
                    for (int tap = 0; tap < 3; tap++)
                        mma_tf32(acc[mf][nt], afr[mf][tap], bfr[tap]);
            }
        }

        // ---- fused attention for this warp's head ----
        if (sc == hw) {
#pragma unroll
            for (int nt = 0; nt < 8; nt++) {
                float a4[4][4];
#pragma unroll
                for (int mg = 0; mg < 4; mg++)
#pragma unroll
                    for (int r = 0; r < 4; r++) a4[mg][r] = 0.f;
#pragma unroll
                for (int kc = 0; kc < 4; kc++) {
                    uint32_t gfr[4][4];
#pragma unroll
                    for (int mg = 0; mg < 4; mg++) {
                        float4 v = *(const float4*)&d_gfrag[((size_t)(b * 8 + hw) * 16 + mg * 4 + kc) * 128 + lane * 4];
                        gfr[mg][0] = __float_as_uint(v.x); gfr[mg][1] = __float_as_uint(v.y);
                        gfr[mg][2] = __float_as_uint(v.z); gfr[mg][3] = __float_as_uint(v.w);
                    }
                    const int gk = kc * 2 + ((lane >> 3) & 1);
                    const int r = 1 + tg * 64 + nt * 8 + (lane & 7);
                    uint32_t bfr[2];
                    ldsm_x2(bfr, bufb + swz(r, gk));
#pragma unroll
                    for (int mg = 0; mg < 4; mg++)
                        mma_tf32(a4[mg], gfr[mg], bfr);
                }
                float m0 = -1e30f, m1 = -1e30f;
#pragma unroll
                for (int mg = 0; mg < 4; mg++) {
                    m0 = fmaxf(m0, fmaxf(a4[mg][0], a4[mg][2]));
                    m1 = fmaxf(m1, fmaxf(a4[mg][1], a4[mg][3]));
                }
#pragma unroll
                for (int d = 4; d <= 16; d <<= 1) {
                    m0 = fmaxf(m0, __shfl_xor_sync(0xffffffffu, m0, d));
                    m1 = fmaxf(m1, __shfl_xor_sync(0xffffffffu, m1, d));
                }
                float z0 = m0 * 0.17677669529663687f + ab;
                float z1 = m1 * 0.17677669529663687f + ab;
                attn0[nt] = 1.f / (1.f + __expf(-z0));
                attn1[nt] = 1.f / (1.f + __expf(-z1));
            }
        }
    }

    // ---- epilogue: (+pb) * attn * mask ----
    const int mk = d_mask_kind;
#pragma unroll
    for (int mf = 0; mf < 2; mf++) {
        const int cob = co0 + cog * 32 + mf * 16 + (lane >> 2);
        const float bias0 = pb[cob], bias1 = pb[cob + 8];
        float* o0 = out + ((size_t)(b * 256 + cob)) * T_;
        float* o1 = o0 + (size_t)8 * T_;
#pragma unroll
        for (int nt = 0; nt < 8; nt++) {
            const int t = t0 + tg * 64 + nt * 8 + 2 * (lane & 3);
            float m0 = mask_at(mask, mk, b, t);
            float m1 = mask_at(mask, mk, b, t + 1);
            float2 v0, v1;
            v0.x = (acc[mf][nt][0] + bias0) * attn0[nt] * m0;
            v0.y = (acc[mf][nt][1] + bias0) * attn1[nt] * m1;
            v1.x = (acc[mf][nt][2] + bias1) * attn0[nt] * m0;
            v1.y = (acc[mf][nt][3] + bias1) * attn1[nt] * m1;
            *(float2*)(o0 + t) = v0;
            *(float2*)(o1 + t) = v1;
        }
    }
}

// ---------------------------------------------------------------------------
extern "C" void kernel_launch(void* const* d_in, const int* in_sizes, int n_in,
                              void* d_out, int out_size)
{
    const float* x     = (const float*)d_in[0];
    const float* guide = (const float*)d_in[1];
    const void*  mask  = (const void*)d_in[2];
    const float* gw    = (const float*)d_in[3];
    const float* gb    = (const float*)d_in[4];
    const float* abias = (const float*)d_in[5];
    const float* pw    = (const float*)d_in[6];
    const float* pb    = (const float*)d_in[7];
    float*       out   = (float*)d_out;

    static int attr_done = 0;
    if (!attr_done) {
        cudaFuncSetAttribute(conv_mma_kernel,
                             cudaFuncAttributeMaxDynamicSharedMemorySize, CONV_TILE_B * 2);
        attr_done = 1;
    }

    mask_classify_kernel<<<1, 256>>>((const uint4*)mask, in_sizes[2] / 16);
    guide_fc_kernel<<<dim3(N_ / 8, B_), 256>>>(guide, gw, gb);
    wfrag_kernel<<<dim3(16, 3), 256>>>(pw);
    gfrag_kernel<<<dim3(8, 16), 256>>>();
    xt_kernel<<<dim3(T_ / 32, CIN_ / 32, B_), dim3(32, 8)>>>(x);
    conv_mma_kernel<<<dim3(T_ / 128, COUT_ / 128, B_), 256, CONV_TILE_B * 2>>>(pb, mask, abias, out);
}

// round 10
// speedup vs baseline: 5.2184x; 1.6525x over previous
#include <cuda_runtime.h>
#include <cuda_fp16.h>
#include <cstdint>

// Problem constants
#define B_    16
#define CIN_  256
#define T_    4096
#define N_    64
#define GC_   224
#define EC_   256
#define H_    8
#define HC_   32
#define COUT_ 256

// Scratch (no cudaMalloc allowed)
__device__ float  d_g[B_ * N_ * EC_];                 // guide embed [b][n][e]
__device__ __half d_xt[(size_t)B_ * T_ * CIN_];       // x^T as fp16 [b][t][ci] (32 MB)
__device__ uint32_t d_wfrag[3 * 16 * 16 * 128];       // fp16x2 A-frags, conv
__device__ uint32_t d_gfrag[16 * 8 * 4 * 2 * 128];    // fp16x2 A-frags, attn
__device__ int    d_mask_kind;                        // 0=int32, 1=float32, 2=byte

// ---------------------------------------------------------------------------
// Helpers (base sm_100-legal: mma.sync sm_80+, ldmatrix sm_75+)
// ---------------------------------------------------------------------------
__device__ __forceinline__ uint32_t smem_u32(const void* p) {
    uint32_t a;
    asm("{ .reg .u64 t; cvta.to.shared.u64 t, %1; cvt.u32.u64 %0, t; }"
        : "=r"(a) : "l"(p));
    return a;
}
__device__ __forceinline__ uint32_t pack_h2(float lo, float hi) {
    __half2 h = __floats2half2_rn(lo, hi);   // .x = lo (lower 16 bits)
    return *(uint32_t*)&h;
}
__device__ __forceinline__ void ldsm_x2(uint32_t* r, uint32_t addr) {
    asm volatile("ldmatrix.sync.aligned.m8n8.x2.shared.b16 {%0, %1}, [%2];"
                 : "=r"(r[0]), "=r"(r[1]) : "r"(addr));
}
__device__ __forceinline__ void mma_f16(float* d, const uint32_t* a, const uint32_t* b) {
    asm volatile(
        "mma.sync.aligned.m16n8k16.row.col.f32.f16.f16.f32 "
        "{%0,%1,%2,%3}, {%4,%5,%6,%7}, {%8,%9}, {%0,%1,%2,%3};"
        : "+f"(d[0]), "+f"(d[1]), "+f"(d[2]), "+f"(d[3])
        : "r"(a[0]), "r"(a[1]), "r"(a[2]), "r"(a[3]), "r"(b[0]), "r"(b[1]));
}
// Swizzled tile: row r = 128B (8 groups of 16B); logical group g at g^(r&7).
__device__ __forceinline__ uint32_t swz(int r, int g) {
    return (uint32_t)((r * 8 + (g ^ (r & 7))) << 4);
}

// ---------------------------------------------------------------------------
// Kernel M: classify mask dtype (proven; vectorized)
// ---------------------------------------------------------------------------
__global__ void mask_classify_kernel(const uint4* __restrict__ m16, int n16)
{
    __shared__ int s_c0, s_c23;
    if (threadIdx.x == 0) { s_c0 = 0; s_c23 = 0; }
    __syncthreads();
    int c0 = 0, c23 = 0;
    for (int i = threadIdx.x; i < n16; i += blockDim.x) {
        uint4 v = m16[i];
        uint32_t ws[4] = { v.x, v.y, v.z, v.w };
#pragma unroll
        for (int k = 0; k < 4; k++) {
            if (ws[k] & 0x000000FFu) c0++;
            if (ws[k] & 0xFFFF0000u) c23++;
        }
    }
    atomicAdd(&s_c0, c0);
    atomicAdd(&s_c23, c23);
    __syncthreads();
    if (threadIdx.x == 0) {
        int kind;
        if (s_c0 > 0 && s_c23 == 0) kind = 0;
        else if (s_c0 == 0 && s_c23 > 0) kind = 1;
        else kind = 2;
        d_mask_kind = kind;
    }
}

__device__ __forceinline__ float mask_at(const void* mp, int kind, int b, int t)
{
    size_t idx = (size_t)b * T_ + t;
    if (kind == 0)      return ((const int*)mp)[idx]   != 0   ? 1.f : 0.f;
    else if (kind == 1) return ((const float*)mp)[idx] != 0.f ? 1.f : 0.f;
    else                return ((const unsigned char*)mp)[idx] ? 1.f : 0.f;
}

// ---------------------------------------------------------------------------
// Kernel A: guide FC (proven R3)
// ---------------------------------------------------------------------------
__global__ __launch_bounds__(256) void guide_fc_kernel(
    const float* __restrict__ guide, const float* __restrict__ gw,
    const float* __restrict__ gb)
{
    const int b  = blockIdx.y;
    const int n0 = blockIdx.x * 8;
    const int e  = threadIdx.x;

    __shared__ float s_guide[8 * GC_];
    __shared__ float s_gw[256 * 33];

    for (int i = threadIdx.x; i < 8 * GC_; i += 256) {
        int nn = i / GC_, k = i % GC_;
        s_guide[i] = guide[((size_t)(b * N_ + n0 + nn)) * GC_ + k];
    }

    float acc[8];
#pragma unroll
    for (int nn = 0; nn < 8; nn++) acc[nn] = 0.f;

    for (int k0 = 0; k0 < GC_; k0 += 32) {
        __syncthreads();
        for (int i = threadIdx.x; i < 256 * 32; i += 256) {
            int ee = i >> 5, j = i & 31;
            s_gw[ee * 33 + j] = gw[ee * GC_ + k0 + j];
        }
        __syncthreads();
#pragma unroll
        for (int j = 0; j < 32; j++) {
            float w = s_gw[e * 33 + j];
#pragma unroll
            for (int nn = 0; nn < 8; nn++)
                acc[nn] += s_guide[nn * GC_ + k0 + j] * w;
        }
    }

    float bias = gb[e];
#pragma unroll
    for (int nn = 0; nn < 8; nn++)
        d_g[((size_t)(b * N_ + n0 + nn)) * EC_ + e] = acc[nn] + bias;
}

// ---------------------------------------------------------------------------
// Kernel X: transpose + fp16 convert: x[b][ci][t] -> d_xt[b][t][ci]
// ---------------------------------------------------------------------------
__global__ void xt_kernel(const float* __restrict__ x)
{
    __shared__ float s[32][33];
    const int b = blockIdx.z, ci0 = blockIdx.y * 32, t0 = blockIdx.x * 32;
    const int tx = threadIdx.x, ty = threadIdx.y;
#pragma unroll
    for (int k = 0; k < 4; k++)
        s[ty + 8 * k][tx] = x[((size_t)(b * CIN_ + ci0 + ty + 8 * k)) * T_ + t0 + tx];
    __syncthreads();
#pragma unroll
    for (int k = 0; k < 4; k++)
        d_xt[((size_t)b * T_ + t0 + ty + 8 * k) * CIN_ + ci0 + tx] =
            __float2half_rn(s[tx][ty + 8 * k]);
}

// ---------------------------------------------------------------------------
// Kernel W: pack conv weights into fp16x2 m16n8k16 A-fragments.
// wfrag[tap][cog16][kc16][lane*4 + r]: a0={A[m][k],A[m][k+1]}, a1=m+8,
// a2=k+8, a3=m+8,k+8;  m=cog*16+(l>>2), k=kc*16+(l&3)*2. pw is [co][ci][tap].
// ---------------------------------------------------------------------------
__global__ __launch_bounds__(256) void wfrag_kernel(const float* __restrict__ pw)
{
    const int cog = blockIdx.x, tap = blockIdx.y;
    for (int i = threadIdx.x; i < 512; i += 256) {
        int kc = i >> 5, lane = i & 31;
        int m = cog * 16 + (lane >> 2);
        int k = kc * 16 + (lane & 3) * 2;
        uint32_t* dst = &d_wfrag[((size_t)(tap * 16 + cog) * 16 + kc) * 128 + lane * 4];
        dst[0] = pack_h2(pw[(size_t)(m * 256 + k) * 3 + tap],
                         pw[(size_t)(m * 256 + k + 1) * 3 + tap]);
        dst[1] = pack_h2(pw[(size_t)((m + 8) * 256 + k) * 3 + tap],
                         pw[(size_t)((m + 8) * 256 + k + 1) * 3 + tap]);
        dst[2] = pack_h2(pw[(size_t)(m * 256 + k + 8) * 3 + tap],
                         pw[(size_t)(m * 256 + k + 9) * 3 + tap]);
        dst[3] = pack_h2(pw[(size_t)((m + 8) * 256 + k + 8) * 3 + tap],
                         pw[(size_t)((m + 8) * 256 + k + 9) * 3 + tap]);
    }
}

// ---------------------------------------------------------------------------
// Kernel G: pack guide embeds into fp16x2 A-fragments per (b, h).
// gfrag[((b*8+h)*4+mg)*2+kc][lane*4+r]: n=mg*16+(l>>2), e=h*32+kc*16+(l&3)*2.
// ---------------------------------------------------------------------------
__global__ __launch_bounds__(256) void gfrag_kernel()
{
    const int h = blockIdx.x, b = blockIdx.y;
    const float* gb = d_g + (size_t)b * N_ * EC_;
    {
        int i = threadIdx.x;                 // exactly 256 = mg4 x kc2 x 32
        int mg = (i >> 6) & 3, kc = (i >> 5) & 1, lane = i & 31;
        int n = mg * 16 + (lane >> 2);
        int e = h * 32 + kc * 16 + (lane & 3) * 2;
        uint32_t* dst = &d_gfrag[(((size_t)(b * 8 + h) * 4 + mg) * 2 + kc) * 128 + lane * 4];
        dst[0] = pack_h2(gb[(size_t)n * 256 + e],       gb[(size_t)n * 256 + e + 1]);
        dst[1] = pack_h2(gb[(size_t)(n + 8) * 256 + e], gb[(size_t)(n + 8) * 256 + e + 1]);
        dst[2] = pack_h2(gb[(size_t)n * 256 + e + 8],   gb[(size_t)n * 256 + e + 9]);
        dst[3] = pack_h2(gb[(size_t)(n + 8) * 256 + e + 8], gb[(size_t)(n + 8) * 256 + e + 9]);
    }
}

// ---------------------------------------------------------------------------
// Kernel C: fused conv1d(k=3) + max-sigmoid attention, fp16 m16n8k16.
// CTA = 128 co x 128 t. Buffer: 130 rows (t0-1..t0+128) x 64 ci (fp16, 128B
// rows, swizzled), double-buffered over 4 ci-chunks. 8 warps = 4 cog x 2 tg.
// Warp's head hw = blockIdx.y*4+cog lives in chunk hw>>1, k-half hw&1.
// ---------------------------------------------------------------------------
#define CONV_ROWS   130
#define CONV_TILE_B (CONV_ROWS * 128)   // 16640 B

__device__ __forceinline__ void conv_stage(const __half* __restrict__ xtb,
                                           char* buf, int sc, int t0, int tid)
{
#pragma unroll
    for (int it = 0; it < 5; it++) {
        int idx = tid + it * 256;           // 1040 x 16B
        if (it < 4 || idx < 1040) {
            int r = idx >> 3, g = idx & 7;
            int gt = t0 - 1 + r;
            uint4 v;
            if (gt >= 0 && gt < T_)
                v = *(const uint4*)(xtb + (size_t)gt * 256 + sc * 64 + g * 8);
            else
                v = make_uint4(0u, 0u, 0u, 0u);
            *(uint4*)(buf + swz(r, g)) = v;
        }
    }
}

__global__ __launch_bounds__(256, 2) void conv_mma_kernel(
    const float* __restrict__ pb, const void* __restrict__ mask,
    const float* __restrict__ abias, float* __restrict__ out)
{
    extern __shared__ __align__(16) char s_dyn[];
    const int b = blockIdx.z, co0 = blockIdx.y * 128, t0 = blockIdx.x * 128;
    const int tid = threadIdx.x, w = tid >> 5, lane = tid & 31;
    const int cog = w & 3, tg = w >> 2;
    const int hw = blockIdx.y * 4 + cog;     // this warp's head
    const uint32_t smb = smem_u32(s_dyn);
    const __half* xtb = d_xt + (size_t)b * T_ * CIN_;

    float acc[2][8][4];
#pragma unroll
    for (int mf = 0; mf < 2; mf++)
#pragma unroll
        for (int nt = 0; nt < 8; nt++)
#pragma unroll
            for (int r = 0; r < 4; r++) acc[mf][nt][r] = 0.f;

    float attn0[8], attn1[8];
    const float ab = abias[hw];

    conv_stage(xtb, s_dyn, 0, t0, tid);

    for (int sc = 0; sc < 4; sc++) {
        __syncthreads();
        if (sc < 3) conv_stage(xtb, s_dyn + ((sc + 1) & 1) * CONV_TILE_B, sc + 1, t0, tid);
        const uint32_t bufb = smb + (sc & 1) * CONV_TILE_B;

        // ---- conv MMAs: 4 kc16 per chunk ----
#pragma unroll
        for (int kc = 0; kc < 4; kc++) {
            const int kc16 = sc * 4 + kc;
            uint32_t afr[2][3][4];
#pragma unroll
            for (int mf = 0; mf < 2; mf++) {
                const int cog16 = blockIdx.y * 8 + cog * 2 + mf;
#pragma unroll
                for (int tap = 0; tap < 3; tap++) {
                    const uint4 v = *(const uint4*)&d_wfrag[((size_t)(tap * 16 + cog16) * 16 + kc16) * 128 + lane * 4];
                    afr[mf][tap][0] = v.x; afr[mf][tap][1] = v.y;
                    afr[mf][tap][2] = v.z; afr[mf][tap][3] = v.w;
                }
            }
            const int gk = kc * 2 + ((lane >> 3) & 1);
#pragma unroll
            for (int nt = 0; nt < 8; nt++) {
                uint32_t bfr[3][2];
#pragma unroll
                for (int s = 0; s < 3; s++) {
                    const int r = tg * 64 + nt * 8 + s + (lane & 7);
                    ldsm_x2(bfr[s], bufb + swz(r, gk));
                }
#pragma unroll
                for (int mf = 0; mf < 2; mf++)
#pragma unroll
                    for (int tap = 0; tap < 3; tap++)
                        mma_f16(acc[mf][nt], afr[mf][tap], bfr[tap]);
            }
        }

        // ---- fused attention for this warp's head ----
        if (sc == (hw >> 1)) {
            const int kb = (hw & 1) * 2;     // k-16 groups within chunk
#pragma unroll
            for (int nt = 0; nt < 8; nt++) {
                float a4[4][4];
#pragma unroll
                for (int mg = 0; mg < 4; mg++)
#pragma unroll
                    for (int r = 0; r < 4; r++) a4[mg][r] = 0.f;
#pragma unroll
                for (int kca = 0; kca < 2; kca++) {
                    const int kc = kb + kca;
                    const int gk = kc * 2 + ((lane >> 3) & 1);
                    const int r = 1 + tg * 64 + nt * 8 + (lane & 7);
                    uint32_t bfr[2];
                    ldsm_x2(bfr, bufb + swz(r, gk));
#pragma unroll
                    for (int mg = 0; mg < 4; mg++) {
                        const uint4 v = *(const uint4*)&d_gfrag[(((size_t)(b * 8 + hw) * 4 + mg) * 2 + kca) * 128 + lane * 4];
                        uint32_t gfr[4] = { v.x, v.y, v.z, v.w };
                        mma_f16(a4[mg], gfr, bfr);
                    }
                }
                float m0 = -1e30f, m1 = -1e30f;
#pragma unroll
                for (int mg = 0; mg < 4; mg++) {
                    m0 = fmaxf(m0, fmaxf(a4[mg][0], a4[mg][2]));
                    m1 = fmaxf(m1, fmaxf(a4[mg][1], a4[mg][3]));
                }
#pragma unroll
                for (int d = 4; d <= 16; d <<= 1) {
                    m0 = fmaxf(m0, __shfl_xor_sync(0xffffffffu, m0, d));
                    m1 = fmaxf(m1, __shfl_xor_sync(0xffffffffu, m1, d));
                }
                float z0 = m0 * 0.17677669529663687f + ab;
                float z1 = m1 * 0.17677669529663687f + ab;
                attn0[nt] = 1.f / (1.f + __expf(-z0));
                attn1[nt] = 1.f / (1.f + __expf(-z1));
            }
        }
    }

    // ---- epilogue: (+pb) * attn * mask ----
    const int mk = d_mask_kind;
#pragma unroll
    for (int mf = 0; mf < 2; mf++) {
        const int cob = co0 + cog * 32 + mf * 16 + (lane >> 2);
        const float bias0 = pb[cob], bias1 = pb[cob + 8];
        float* o0 = out + ((size_t)(b * 256 + cob)) * T_;
        float* o1 = o0 + (size_t)8 * T_;
#pragma unroll
        for (int nt = 0; nt < 8; nt++) {
            const int t = t0 + tg * 64 + nt * 8 + 2 * (lane & 3);
            float m0 = mask_at(mask, mk, b, t);
            float m1 = mask_at(mask, mk, b, t + 1);
            float2 v0, v1;
            v0.x = (acc[mf][nt][0] + bias0) * attn0[nt] * m0;
            v0.y = (acc[mf][nt][1] + bias0) * attn1[nt] * m1;
            v1.x = (acc[mf][nt][2] + bias1) * attn0[nt] * m0;
            v1.y = (acc[mf][nt][3] + bias1) * attn1[nt] * m1;
            *(float2*)(o0 + t) = v0;
            *(float2*)(o1 + t) = v1;
        }
    }
}

// ---------------------------------------------------------------------------
extern "C" void kernel_launch(void* const* d_in, const int* in_sizes, int n_in,
                              void* d_out, int out_size)
{
    const float* x     = (const float*)d_in[0];
    const float* guide = (const float*)d_in[1];
    const void*  mask  = (const void*)d_in[2];
    const float* gw    = (const float*)d_in[3];
    const float* gb    = (const float*)d_in[4];
    const float* abias = (const float*)d_in[5];
    const float* pw    = (const float*)d_in[6];
    const float* pb    = (const float*)d_in[7];
    float*       out   = (float*)d_out;

    static int attr_done = 0;
    if (!attr_done) {
        cudaFuncSetAttribute(conv_mma_kernel,
                             cudaFuncAttributeMaxDynamicSharedMemorySize, CONV_TILE_B * 2);
        attr_done = 1;
    }

    mask_classify_kernel<<<1, 256>>>((const uint4*)mask, in_sizes[2] / 16);
    guide_fc_kernel<<<dim3(N_ / 8, B_), 256>>>(guide, gw, gb);
    wfrag_kernel<<<dim3(16, 3), 256>>>(pw);
    gfrag_kernel<<<dim3(8, 16), 256>>>();
    xt_kernel<<<dim3(T_ / 32, CIN_ / 32, B_), dim3(32, 8)>>>(x);
    conv_mma_kernel<<<dim3(T_ / 128, COUT_ / 128, B_), 256, CONV_TILE_B * 2>>>(pb, mask, abias, out);
}

// round 11
// speedup vs baseline: 5.6545x; 1.0836x over previous
#include <cuda_runtime.h>
#include <cuda_fp16.h>
#include <cstdint>

// Problem constants
#define B_    16
#define CIN_  256
#define T_    4096
#define N_    64
#define GC_   224
#define EC_   256
#define H_    8
#define HC_   32
#define COUT_ 256

// Scratch (no cudaMalloc allowed)
__device__ __half d_xt[(size_t)B_ * T_ * CIN_];       // x^T as fp16 [b][t][ci] (32 MB)
__device__ uint32_t d_wfrag[3 * 16 * 16 * 128];       // fp16x2 A-frags, conv
__device__ uint32_t d_gfrag[16 * 8 * 4 * 2 * 128];    // fp16x2 A-frags, attn
__device__ int    d_mask_kind;                        // 0=int32, 1=float32, 2=byte

// ---------------------------------------------------------------------------
// Helpers (base sm_100-legal: mma.sync sm_80+, ldmatrix sm_75+)
// ---------------------------------------------------------------------------
__device__ __forceinline__ uint32_t smem_u32(const void* p) {
    uint32_t a;
    asm("{ .reg .u64 t; cvta.to.shared.u64 t, %1; cvt.u32.u64 %0, t; }"
        : "=r"(a) : "l"(p));
    return a;
}
__device__ __forceinline__ uint32_t pack_h2(float lo, float hi) {
    __half2 h = __floats2half2_rn(lo, hi);   // .x = lo (lower 16 bits)
    return *(uint32_t*)&h;
}
__device__ __forceinline__ void ldsm_x2(uint32_t* r, uint32_t addr) {
    asm volatile("ldmatrix.sync.aligned.m8n8.x2.shared.b16 {%0, %1}, [%2];"
                 : "=r"(r[0]), "=r"(r[1]) : "r"(addr));
}
__device__ __forceinline__ void mma_f16(float* d, const uint32_t* a, const uint32_t* b) {
    asm volatile(
        "mma.sync.aligned.m16n8k16.row.col.f32.f16.f16.f32 "
        "{%0,%1,%2,%3}, {%4,%5,%6,%7}, {%8,%9}, {%0,%1,%2,%3};"
        : "+f"(d[0]), "+f"(d[1]), "+f"(d[2]), "+f"(d[3])
        : "r"(a[0]), "r"(a[1]), "r"(a[2]), "r"(a[3]), "r"(b[0]), "r"(b[1]));
}
// Swizzled tile: row r = 128B (8 groups of 16B); logical group g at g^(r&7).
__device__ __forceinline__ uint32_t swz(int r, int g) {
    return (uint32_t)((r * 8 + (g ^ (r & 7))) << 4);
}

__device__ __forceinline__ float mask_at(const void* mp, int kind, int b, int t)
{
    size_t idx = (size_t)b * T_ + t;
    if (kind == 0)      return ((const int*)mp)[idx]   != 0   ? 1.f : 0.f;
    else if (kind == 1) return ((const float*)mp)[idx] != 0.f ? 1.f : 0.f;
    else                return ((const unsigned char*)mp)[idx] ? 1.f : 0.f;
}

// ---------------------------------------------------------------------------
// Kernel P1: role-dispatched prep.
//   block 0       : mask classify (proven logic, vectorized)
//   blocks 1..48  : wfrag pack (proven R10)
//   blocks 49..   : xt transpose + fp16 convert (proven R10)
// ---------------------------------------------------------------------------
#define P1_XT0 49
__global__ __launch_bounds__(256) void prep1_kernel(
    const float* __restrict__ x, const float* __restrict__ pw,
    const uint4* __restrict__ m16, int n16)
{
    __shared__ float s[32][33];
    const int bid = blockIdx.x, tid = threadIdx.x;

    if (bid == 0) {
        // ---- mask classify ----
        __shared__ int s_c0, s_c23;
        if (tid == 0) { s_c0 = 0; s_c23 = 0; }
        __syncthreads();
        int c0 = 0, c23 = 0;
        for (int i = tid; i < n16; i += 256) {
            uint4 v = m16[i];
            uint32_t ws[4] = { v.x, v.y, v.z, v.w };
#pragma unroll
            for (int k = 0; k < 4; k++) {
                if (ws[k] & 0x000000FFu) c0++;
                if (ws[k] & 0xFFFF0000u) c23++;
            }
        }
        atomicAdd(&s_c0, c0);
        atomicAdd(&s_c23, c23);
        __syncthreads();
        if (tid == 0) {
            int kind;
            if (s_c0 > 0 && s_c23 == 0) kind = 0;
            else if (s_c0 == 0 && s_c23 > 0) kind = 1;
            else kind = 2;
            d_mask_kind = kind;
        }
    } else if (bid <= 48) {
        // ---- wfrag pack ----
        const int r48 = bid - 1;
        const int cog = r48 & 15, tap = r48 >> 4;
        for (int i = tid; i < 512; i += 256) {
            int kc = i >> 5, lane = i & 31;
            int m = cog * 16 + (lane >> 2);
            int k = kc * 16 + (lane & 3) * 2;
            uint32_t* dst = &d_wfrag[((size_t)(tap * 16 + cog) * 16 + kc) * 128 + lane * 4];
            dst[0] = pack_h2(pw[(size_t)(m * 256 + k) * 3 + tap],
                             pw[(size_t)(m * 256 + k + 1) * 3 + tap]);
            dst[1] = pack_h2(pw[(size_t)((m + 8) * 256 + k) * 3 + tap],
                             pw[(size_t)((m + 8) * 256 + k + 1) * 3 + tap]);
            dst[2] = pack_h2(pw[(size_t)(m * 256 + k + 8) * 3 + tap],
                             pw[(size_t)(m * 256 + k + 9) * 3 + tap]);
            dst[3] = pack_h2(pw[(size_t)((m + 8) * 256 + k + 8) * 3 + tap],
                             pw[(size_t)((m + 8) * 256 + k + 9) * 3 + tap]);
        }
    } else {
        // ---- xt transpose ----
        const int xb = bid - P1_XT0;           // 0 .. 16383
        const int b = xb >> 10;
        const int ci0 = ((xb & 1023) >> 7) * 32;
        const int t0 = ((xb & 127)) * 32;
        const int tx = tid & 31, ty = tid >> 5;
#pragma unroll
        for (int k = 0; k < 4; k++)
            s[ty + 8 * k][tx] = x[((size_t)(b * CIN_ + ci0 + ty + 8 * k)) * T_ + t0 + tx];
        __syncthreads();
#pragma unroll
        for (int k = 0; k < 4; k++)
            d_xt[((size_t)b * T_ + t0 + ty + 8 * k) * CIN_ + ci0 + tx] =
                __float2half_rn(s[tx][ty + 8 * k]);
    }
}

// ---------------------------------------------------------------------------
// Kernel P2: guide FC (proven R3) with gfrag packing fused in.
// Block (n-group of 8, b): computes g[n0..n0+7][all e] then packs the
// half-fragments whose n rows fall in this window (regs {0,2} if n0%16==0,
// {1,3} if n0%16==8) — disjoint u32 writes across blocks.
// ---------------------------------------------------------------------------
__global__ __launch_bounds__(256) void prep2_kernel(
    const float* __restrict__ guide, const float* __restrict__ gw,
    const float* __restrict__ gb)
{
    const int b  = blockIdx.y;
    const int n0 = blockIdx.x * 8;
    const int e  = threadIdx.x;

    __shared__ float s_guide[8 * GC_];
    __shared__ float s_gw[256 * 33];
    __shared__ float s_g[8][256];

    for (int i = threadIdx.x; i < 8 * GC_; i += 256) {
        int nn = i / GC_, k = i % GC_;
        s_guide[i] = guide[((size_t)(b * N_ + n0 + nn)) * GC_ + k];
    }

    float acc[8];
#pragma unroll
    for (int nn = 0; nn < 8; nn++) acc[nn] = 0.f;

    for (int k0 = 0; k0 < GC_; k0 += 32) {
        __syncthreads();
        for (int i = threadIdx.x; i < 256 * 32; i += 256) {
            int ee = i >> 5, j = i & 31;
            s_gw[ee * 33 + j] = gw[ee * GC_ + k0 + j];
        }
        __syncthreads();
#pragma unroll
        for (int j = 0; j < 32; j++) {
            float w = s_gw[e * 33 + j];
#pragma unroll
            for (int nn = 0; nn < 8; nn++)
                acc[nn] += s_guide[nn * GC_ + k0 + j] * w;
        }
    }

    const float bias = gb[e];
#pragma unroll
    for (int nn = 0; nn < 8; nn++) s_g[nn][e] = acc[nn] + bias;
    __syncthreads();

    // ---- pack gfrag half-fragments for rows n0..n0+7 ----
    const int mg = n0 >> 4;
    const int rbase = (n0 & 8) ? 1 : 0;      // regs {1,3} vs {0,2}
    for (int i = threadIdx.x; i < 512; i += 256) {
        // i = h(8) x kc(2) x lane(32)
        int h = i >> 6, kc = (i >> 5) & 1, lane = i & 31;
        int nn = (lane >> 2);                // row within this 8-n window
        int ee = h * 32 + kc * 16 + (lane & 3) * 2;
        uint32_t* dst = &d_gfrag[(((size_t)(b * 8 + h) * 4 + mg) * 2 + kc) * 128 + lane * 4];
        dst[rbase]     = pack_h2(s_g[nn][ee],     s_g[nn][ee + 1]);
        dst[rbase + 2] = pack_h2(s_g[nn][ee + 8], s_g[nn][ee + 9]);
    }
}

// ---------------------------------------------------------------------------
// Kernel C: fused conv1d(k=3) + max-sigmoid attention, fp16 m16n8k16
// (proven R10, unchanged).
// ---------------------------------------------------------------------------
#define CONV_ROWS   130
#define CONV_TILE_B (CONV_ROWS * 128)   // 16640 B

__device__ __forceinline__ void conv_stage(const __half* __restrict__ xtb,
                                           char* buf, int sc, int t0, int tid)
{
#pragma unroll
    for (int it = 0; it < 5; it++) {
        int idx = tid + it * 256;           // 1040 x 16B
        if (it < 4 || idx < 1040) {
            int r = idx >> 3, g = idx & 7;
            int gt = t0 - 1 + r;
            uint4 v;
            if (gt >= 0 && gt < T_)
                v = *(const uint4*)(xtb + (size_t)gt * 256 + sc * 64 + g * 8);
            else
                v = make_uint4(0u, 0u, 0u, 0u);
            *(uint4*)(buf + swz(r, g)) = v;
        }
    }
}

__global__ __launch_bounds__(256, 2) void conv_mma_kernel(
    const float* __restrict__ pb, const void* __restrict__ mask,
    const float* __restrict__ abias, float* __restrict__ out)
{
    extern __shared__ __align__(16) char s_dyn[];
    const int b = blockIdx.z, co0 = blockIdx.y * 128, t0 = blockIdx.x * 128;
    const int tid = threadIdx.x, w = tid >> 5, lane = tid & 31;
    const int cog = w & 3, tg = w >> 2;
    const int hw = blockIdx.y * 4 + cog;     // this warp's head
    const uint32_t smb = smem_u32(s_dyn);
    const __half* xtb = d_xt + (size_t)b * T_ * CIN_;

    float acc[2][8][4];
#pragma unroll
    for (int mf = 0; mf < 2; mf++)
#pragma unroll
        for (int nt = 0; nt < 8; nt++)
#pragma unroll
            for (int r = 0; r < 4; r++) acc[mf][nt][r] = 0.f;

    float attn0[8], attn1[8];
    const float ab = abias[hw];

    conv_stage(xtb, s_dyn, 0, t0, tid);

    for (int sc = 0; sc < 4; sc++) {
        __syncthreads();
        if (sc < 3) conv_stage(xtb, s_dyn + ((sc + 1) & 1) * CONV_TILE_B, sc + 1, t0, tid);
        const uint32_t bufb = smb + (sc & 1) * CONV_TILE_B;

        // ---- conv MMAs: 4 kc16 per chunk ----
#pragma unroll
        for (int kc = 0; kc < 4; kc++) {
            const int kc16 = sc * 4 + kc;
            uint32_t afr[2][3][4];
#pragma unroll
            for (int mf = 0; mf < 2; mf++) {
                const int cog16 = blockIdx.y * 8 + cog * 2 + mf;
#pragma unroll
                for (int tap = 0; tap < 3; tap++) {
                    const uint4 v = *(const uint4*)&d_wfrag[((size_t)(tap * 16 + cog16) * 16 + kc16) * 128 + lane * 4];
                    afr[mf][tap][0] = v.x; afr[mf][tap][1] = v.y;
                    afr[mf][tap][2] = v.z; afr[mf][tap][3] = v.w;
                }
            }
            const int gk = kc * 2 + ((lane >> 3) & 1);
#pragma unroll
            for (int nt = 0; nt < 8; nt++) {
                uint32_t bfr[3][2];
#pragma unroll
                for (int s = 0; s < 3; s++) {
                    const int r = tg * 64 + nt * 8 + s + (lane & 7);
                    ldsm_x2(bfr[s], bufb + swz(r, gk));
                }
#pragma unroll
                for (int mf = 0; mf < 2; mf++)
#pragma unroll
                    for (int tap = 0; tap < 3; tap++)
                        mma_f16(acc[mf][nt], afr[mf][tap], bfr[tap]);
            }
        }

        // ---- fused attention for this warp's head ----
        if (sc == (hw >> 1)) {
            const int kb = (hw & 1) * 2;     // k-16 groups within chunk
#pragma unroll
            for (int nt = 0; nt < 8; nt++) {
                float a4[4][4];
#pragma unroll
                for (int mg = 0; mg < 4; mg++)
#pragma unroll
                    for (int r = 0; r < 4; r++) a4[mg][r] = 0.f;
#pragma unroll
                for (int kca = 0; kca < 2; kca++) {
                    const int kc = kb + kca;
                    const int gk = kc * 2 + ((lane >> 3) & 1);
                    const int r = 1 + tg * 64 + nt * 8 + (lane & 7);
                    uint32_t bfr[2];
                    ldsm_x2(bfr, bufb + swz(r, gk));
#pragma unroll
                    for (int mg = 0; mg < 4; mg++) {
                        const uint4 v = *(const uint4*)&d_gfrag[(((size_t)(b * 8 + hw) * 4 + mg) * 2 + kca) * 128 + lane * 4];
                        uint32_t gfr[4] = { v.x, v.y, v.z, v.w };
                        mma_f16(a4[mg], gfr, bfr);
                    }
                }
                float m0 = -1e30f, m1 = -1e30f;
#pragma unroll
                for (int mg = 0; mg < 4; mg++) {
                    m0 = fmaxf(m0, fmaxf(a4[mg][0], a4[mg][2]));
                    m1 = fmaxf(m1, fmaxf(a4[mg][1], a4[mg][3]));
                }
#pragma unroll
                for (int d = 4; d <= 16; d <<= 1) {
                    m0 = fmaxf(m0, __shfl_xor_sync(0xffffffffu, m0, d));
                    m1 = fmaxf(m1, __shfl_xor_sync(0xffffffffu, m1, d));
                }
                float z0 = m0 * 0.17677669529663687f + ab;
                float z1 = m1 * 0.17677669529663687f + ab;
                attn0[nt] = 1.f / (1.f + __expf(-z0));
                attn1[nt] = 1.f / (1.f + __expf(-z1));
            }
        }
    }

    // ---- epilogue: (+pb) * attn * mask ----
    const int mk = d_mask_kind;
#pragma unroll
    for (int mf = 0; mf < 2; mf++) {
        const int cob = co0 + cog * 32 + mf * 16 + (lane >> 2);
        const float bias0 = pb[cob], bias1 = pb[cob + 8];
        float* o0 = out + ((size_t)(b * 256 + cob)) * T_;
        float* o1 = o0 + (size_t)8 * T_;
#pragma unroll
        for (int nt = 0; nt < 8; nt++) {
            const int t = t0 + tg * 64 + nt * 8 + 2 * (lane & 3);
            float m0 = mask_at(mask, mk, b, t);
            float m1 = mask_at(mask, mk, b, t + 1);
            float2 v0, v1;
            v0.x = (acc[mf][nt][0] + bias0) * attn0[nt] * m0;
            v0.y = (acc[mf][nt][1] + bias0) * attn1[nt] * m1;
            v1.x = (acc[mf][nt][2] + bias1) * attn0[nt] * m0;
            v1.y = (acc[mf][nt][3] + bias1) * attn1[nt] * m1;
            *(float2*)(o0 + t) = v0;
            *(float2*)(o1 + t) = v1;
        }
    }
}

// ---------------------------------------------------------------------------
extern "C" void kernel_launch(void* const* d_in, const int* in_sizes, int n_in,
                              void* d_out, int out_size)
{
    const float* x     = (const float*)d_in[0];
    const float* guide = (const float*)d_in[1];
    const void*  mask  = (const void*)d_in[2];
    const float* gw    = (const float*)d_in[3];
    const float* gb    = (const float*)d_in[4];
    const float* abias = (const float*)d_in[5];
    const float* pw    = (const float*)d_in[6];
    const float* pb    = (const float*)d_in[7];
    float*       out   = (float*)d_out;

    static int attr_done = 0;
    if (!attr_done) {
        cudaFuncSetAttribute(conv_mma_kernel,
                             cudaFuncAttributeMaxDynamicSharedMemorySize, CONV_TILE_B * 2);
        attr_done = 1;
    }

    prep1_kernel<<<P1_XT0 + 16384, 256>>>(x, pw, (const uint4*)mask, in_sizes[2] / 16);
    prep2_kernel<<<dim3(N_ / 8, B_), 256>>>(guide, gw, gb);
    conv_mma_kernel<<<dim3(T_ / 128, COUT_ / 128, B_), 256, CONV_TILE_B * 2>>>(pb, mask, abias, out);
}

// round 12
// speedup vs baseline: 5.8550x; 1.0354x over previous
#include <cuda_runtime.h>
#include <cuda_fp16.h>
#include <cstdint>

// Problem constants
#define B_    16
#define CIN_  256
#define T_    4096
#define N_    64
#define GC_   224
#define EC_   256
#define H_    8
#define HC_   32
#define COUT_ 256

// Scratch (no cudaMalloc allowed)
__device__ __half d_xt[(size_t)B_ * T_ * CIN_];       // x^T as fp16 [b][t][ci] (32 MB)
__device__ uint32_t d_wfrag[3 * 16 * 16 * 128];       // fp16x2 A-frags, conv
__device__ uint32_t d_gfrag[16 * 8 * 4 * 2 * 128];    // fp16x2 A-frags, attn
__device__ int    d_mask_kind;                        // 0=int32, 1=float32, 2=byte

// ---------------------------------------------------------------------------
// Helpers (base sm_100-legal: mma.sync sm_80+, ldmatrix sm_75+, cp.async sm_80+)
// ---------------------------------------------------------------------------
__device__ __forceinline__ uint32_t smem_u32(const void* p) {
    uint32_t a;
    asm("{ .reg .u64 t; cvta.to.shared.u64 t, %1; cvt.u32.u64 %0, t; }"
        : "=r"(a) : "l"(p));
    return a;
}
__device__ __forceinline__ uint32_t pack_h2(float lo, float hi) {
    __half2 h = __floats2half2_rn(lo, hi);   // .x = lo (lower 16 bits)
    return *(uint32_t*)&h;
}
__device__ __forceinline__ void ldsm_x2(uint32_t* r, uint32_t addr) {
    asm volatile("ldmatrix.sync.aligned.m8n8.x2.shared.b16 {%0, %1}, [%2];"
                 : "=r"(r[0]), "=r"(r[1]) : "r"(addr));
}
__device__ __forceinline__ void mma_f16(float* d, const uint32_t* a, const uint32_t* b) {
    asm volatile(
        "mma.sync.aligned.m16n8k16.row.col.f32.f16.f16.f32 "
        "{%0,%1,%2,%3}, {%4,%5,%6,%7}, {%8,%9}, {%0,%1,%2,%3};"
        : "+f"(d[0]), "+f"(d[1]), "+f"(d[2]), "+f"(d[3])
        : "r"(a[0]), "r"(a[1]), "r"(a[2]), "r"(a[3]), "r"(b[0]), "r"(b[1]));
}
// cp.async 16B with zero-fill when invalid (src-size = 0)
__device__ __forceinline__ void cp16z(uint32_t dst, const void* src, bool valid) {
    int sz = valid ? 16 : 0;
    asm volatile("cp.async.cg.shared.global [%0], [%1], 16, %2;"
                 :: "r"(dst), "l"(src), "r"(sz) : "memory");
}
#define CP_COMMIT() asm volatile("cp.async.commit_group;" ::: "memory")
#define CP_WAIT0()  asm volatile("cp.async.wait_group 0;" ::: "memory")

// Swizzled 512B-row tile (32 groups of 16B per row): logical group g stored at
// (g&24) | ((g&7) ^ (r&7)). Bank of group g' = (g'*4)&31 depends only on g'&7,
// so ldmatrix's 8 rows at fixed g hit 8 distinct bank-groups.
__device__ __forceinline__ uint32_t swz512(int r, int g) {
    return (uint32_t)(r * 512 + (((g & 24) | ((g & 7) ^ (r & 7))) << 4));
}

__device__ __forceinline__ float mask_at(const void* mp, int kind, int b, int t)
{
    size_t idx = (size_t)b * T_ + t;
    if (kind == 0)      return ((const int*)mp)[idx]   != 0   ? 1.f : 0.f;
    else if (kind == 1) return ((const float*)mp)[idx] != 0.f ? 1.f : 0.f;
    else                return ((const unsigned char*)mp)[idx] ? 1.f : 0.f;
}

// ---------------------------------------------------------------------------
// Kernel P1: role-dispatched prep: wfrag pack (blocks 0..47) + xt (rest)
// ---------------------------------------------------------------------------
#define P1_XT0 48
__global__ __launch_bounds__(256) void prep1_kernel(
    const float* __restrict__ x, const float* __restrict__ pw)
{
    __shared__ float s[32][33];
    const int bid = blockIdx.x, tid = threadIdx.x;

    if (bid < 48) {
        // ---- wfrag pack (proven R10) ----
        const int cog = bid & 15, tap = bid >> 4;
        for (int i = tid; i < 512; i += 256) {
            int kc = i >> 5, lane = i & 31;
            int m = cog * 16 + (lane >> 2);
            int k = kc * 16 + (lane & 3) * 2;
            uint32_t* dst = &d_wfrag[((size_t)(tap * 16 + cog) * 16 + kc) * 128 + lane * 4];
            dst[0] = pack_h2(pw[(size_t)(m * 256 + k) * 3 + tap],
                             pw[(size_t)(m * 256 + k + 1) * 3 + tap]);
            dst[1] = pack_h2(pw[(size_t)((m + 8) * 256 + k) * 3 + tap],
                             pw[(size_t)((m + 8) * 256 + k + 1) * 3 + tap]);
            dst[2] = pack_h2(pw[(size_t)(m * 256 + k + 8) * 3 + tap],
                             pw[(size_t)(m * 256 + k + 9) * 3 + tap]);
            dst[3] = pack_h2(pw[(size_t)((m + 8) * 256 + k + 8) * 3 + tap],
                             pw[(size_t)((m + 8) * 256 + k + 9) * 3 + tap]);
        }
    } else {
        // ---- xt transpose + fp16 convert (proven R10) ----
        const int xb = bid - P1_XT0;           // 0 .. 16383
        const int b = xb >> 10;
        const int ci0 = ((xb & 1023) >> 7) * 32;
        const int t0 = ((xb & 127)) * 32;
        const int tx = tid & 31, ty = tid >> 5;
#pragma unroll
        for (int k = 0; k < 4; k++)
            s[ty + 8 * k][tx] = x[((size_t)(b * CIN_ + ci0 + ty + 8 * k)) * T_ + t0 + tx];
        __syncthreads();
#pragma unroll
        for (int k = 0; k < 4; k++)
            d_xt[((size_t)b * T_ + t0 + ty + 8 * k) * CIN_ + ci0 + tx] =
                __float2half_rn(s[tx][ty + 8 * k]);
    }
}

// ---------------------------------------------------------------------------
// Kernel P2: guide FC + fused gfrag packing (proven R11)
// ---------------------------------------------------------------------------
__global__ __launch_bounds__(256) void prep2_kernel(
    const float* __restrict__ guide, const float* __restrict__ gw,
    const float* __restrict__ gb)
{
    const int b  = blockIdx.y;
    const int n0 = blockIdx.x * 8;
    const int e  = threadIdx.x;

    __shared__ float s_guide[8 * GC_];
    __shared__ float s_gw[256 * 33];
    __shared__ float s_g[8][256];

    for (int i = threadIdx.x; i < 8 * GC_; i += 256) {
        int nn = i / GC_, k = i % GC_;
        s_guide[i] = guide[((size_t)(b * N_ + n0 + nn)) * GC_ + k];
    }

    float acc[8];
#pragma unroll
    for (int nn = 0; nn < 8; nn++) acc[nn] = 0.f;

    for (int k0 = 0; k0 < GC_; k0 += 32) {
        __syncthreads();
        for (int i = threadIdx.x; i < 256 * 32; i += 256) {
            int ee = i >> 5, j = i & 31;
            s_gw[ee * 33 + j] = gw[ee * GC_ + k0 + j];
        }
        __syncthreads();
#pragma unroll
        for (int j = 0; j < 32; j++) {
            float w = s_gw[e * 33 + j];
#pragma unroll
            for (int nn = 0; nn < 8; nn++)
                acc[nn] += s_guide[nn * GC_ + k0 + j] * w;
        }
    }

    const float bias = gb[e];
#pragma unroll
    for (int nn = 0; nn < 8; nn++) s_g[nn][e] = acc[nn] + bias;
    __syncthreads();

    const int mg = n0 >> 4;
    const int rbase = (n0 & 8) ? 1 : 0;      // regs {1,3} vs {0,2}
    for (int i = threadIdx.x; i < 512; i += 256) {
        int h = i >> 6, kc = (i >> 5) & 1, lane = i & 31;
        int nn = (lane >> 2);
        int ee = h * 32 + kc * 16 + (lane & 3) * 2;
        uint32_t* dst = &d_gfrag[(((size_t)(b * 8 + h) * 4 + mg) * 2 + kc) * 128 + lane * 4];
        dst[rbase]     = pack_h2(s_g[nn][ee],     s_g[nn][ee + 1]);
        dst[rbase + 2] = pack_h2(s_g[nn][ee + 8], s_g[nn][ee + 9]);
    }
}

// ---------------------------------------------------------------------------
// Kernel P3: mask classify (proven; tiny, 3rd launch so conv is #4 for ncu)
// ---------------------------------------------------------------------------
__global__ void prep3_kernel(const uint4* __restrict__ m16, int n16)
{
    __shared__ int s_c0, s_c23;
    if (threadIdx.x == 0) { s_c0 = 0; s_c23 = 0; }
    __syncthreads();
    int c0 = 0, c23 = 0;
    for (int i = threadIdx.x; i < n16; i += blockDim.x) {
        uint4 v = m16[i];
        uint32_t ws[4] = { v.x, v.y, v.z, v.w };
#pragma unroll
        for (int k = 0; k < 4; k++) {
            if (ws[k] & 0x000000FFu) c0++;
            if (ws[k] & 0xFFFF0000u) c23++;
        }
    }
    atomicAdd(&s_c0, c0);
    atomicAdd(&s_c23, c23);
    __syncthreads();
    if (threadIdx.x == 0) {
        int kind;
        if (s_c0 > 0 && s_c23 == 0) kind = 0;
        else if (s_c0 == 0 && s_c23 > 0) kind = 1;
        else kind = 2;
        d_mask_kind = kind;
    }
}

// ---------------------------------------------------------------------------
// Kernel C: fused conv1d(k=3) + max-sigmoid attention, fp16 m16n8k16.
// CTA = 128 co x 128 t. SINGLE buffer: 130 rows (t0-1..t0+128) x 256 ci fp16
// (512B rows, swizzled), staged once via cp.async, one __syncthreads, then
// an uninterrupted 16-kc16 compute loop; attn sub-GEMM after (tile resident).
// 8 warps = 4 cog x 2 tg. Warp's head hw = blockIdx.y*4+cog.
// ---------------------------------------------------------------------------
#define CONV_ROWS   130
#define CONV_TILE_B (CONV_ROWS * 512)   // 66560 B

__global__ __launch_bounds__(256, 2) void conv_mma_kernel(
    const float* __restrict__ pb, const void* __restrict__ mask,
    const float* __restrict__ abias, float* __restrict__ out)
{
    extern __shared__ __align__(16) char s_dyn[];
    const int b = blockIdx.z, co0 = blockIdx.y * 128, t0 = blockIdx.x * 128;
    const int tid = threadIdx.x, w = tid >> 5, lane = tid & 31;
    const int cog = w & 3, tg = w >> 2;
    const int hw = blockIdx.y * 4 + cog;     // this warp's head
    const uint32_t smb = smem_u32(s_dyn);
    const __half* xtb = d_xt + (size_t)b * T_ * CIN_;

    // ---- stage entire tile with cp.async (zero-fill halo) ----
#pragma unroll
    for (int it = 0; it < 17; it++) {
        int idx = tid + it * 256;            // 4160 x 16B
        if (it < 16 || idx < 4160) {
            int r = idx >> 5, g = idx & 31;
            int gt = t0 - 1 + r;
            int gtc = gt < 0 ? 0 : (gt >= T_ ? T_ - 1 : gt);
            cp16z(smb + swz512(r, g), xtb + (size_t)gtc * 256 + g * 8,
                  gt >= 0 && gt < T_);
        }
    }
    CP_COMMIT();

    float acc[2][8][4];
#pragma unroll
    for (int mf = 0; mf < 2; mf++)
#pragma unroll
        for (int nt = 0; nt < 8; nt++)
#pragma unroll
            for (int r = 0; r < 4; r++) acc[mf][nt][r] = 0.f;

    CP_WAIT0();
    __syncthreads();

    // ---- conv MMAs over all 16 kc16 ----
#pragma unroll 4
    for (int kc16 = 0; kc16 < 16; kc16++) {
        uint32_t afr[2][3][4];
#pragma unroll
        for (int mf = 0; mf < 2; mf++) {
            const int cog16 = blockIdx.y * 8 + cog * 2 + mf;
#pragma unroll
            for (int tap = 0; tap < 3; tap++) {
                const uint4 v = *(const uint4*)&d_wfrag[((size_t)(tap * 16 + cog16) * 16 + kc16) * 128 + lane * 4];
                afr[mf][tap][0] = v.x; afr[mf][tap][1] = v.y;
                afr[mf][tap][2] = v.z; afr[mf][tap][3] = v.w;
            }
        }
        const int gk = kc16 * 2 + ((lane >> 3) & 1);
#pragma unroll
        for (int nt = 0; nt < 8; nt++) {
            uint32_t bfr[3][2];
#pragma unroll
            for (int s = 0; s < 3; s++) {
                const int r = tg * 64 + nt * 8 + s + (lane & 7);
                ldsm_x2(bfr[s], smb + swz512(r, gk));
            }
#pragma unroll
            for (int mf = 0; mf < 2; mf++)
#pragma unroll
                for (int tap = 0; tap < 3; tap++)
                    mma_f16(acc[mf][nt], afr[mf][tap], bfr[tap]);
        }
    }

    // ---- attention for this warp's head (tile fully resident) ----
    float attn0[8], attn1[8];
    {
        const float ab = abias[hw];
#pragma unroll
        for (int nt = 0; nt < 8; nt++) {
            float a4[4][4];
#pragma unroll
            for (int mg = 0; mg < 4; mg++)
#pragma unroll
                for (int r = 0; r < 4; r++) a4[mg][r] = 0.f;
#pragma unroll
            for (int kca = 0; kca < 2; kca++) {
                const int kc16 = hw * 2 + kca;
                const int gk = kc16 * 2 + ((lane >> 3) & 1);
                const int r = 1 + tg * 64 + nt * 8 + (lane & 7);
                uint32_t bfr[2];
                ldsm_x2(bfr, smb + swz512(r, gk));
#pragma unroll
                for (int mg = 0; mg < 4; mg++) {
                    const uint4 v = *(const uint4*)&d_gfrag[(((size_t)(b * 8 + hw) * 4 + mg) * 2 + kca) * 128 + lane * 4];
                    uint32_t gfr[4] = { v.x, v.y, v.z, v.w };
                    mma_f16(a4[mg], gfr, bfr);
                }
            }
            float m0 = -1e30f, m1 = -1e30f;
#pragma unroll
            for (int mg = 0; mg < 4; mg++) {
                m0 = fmaxf(m0, fmaxf(a4[mg][0], a4[mg][2]));
                m1 = fmaxf(m1, fmaxf(a4[mg][1], a4[mg][3]));
            }
#pragma unroll
            for (int d = 4; d <= 16; d <<= 1) {
                m0 = fmaxf(m0, __shfl_xor_sync(0xffffffffu, m0, d));
                m1 = fmaxf(m1, __shfl_xor_sync(0xffffffffu, m1, d));
            }
            float z0 = m0 * 0.17677669529663687f + ab;
            float z1 = m1 * 0.17677669529663687f + ab;
            attn0[nt] = 1.f / (1.f + __expf(-z0));
            attn1[nt] = 1.f / (1.f + __expf(-z1));
        }
    }

    // ---- epilogue: (+pb) * attn * mask ----
    const int mk = d_mask_kind;
#pragma unroll
    for (int mf = 0; mf < 2; mf++) {
        const int cob = co0 + cog * 32 + mf * 16 + (lane >> 2);
        const float bias0 = pb[cob], bias1 = pb[cob + 8];
        float* o0 = out + ((size_t)(b * 256 + cob)) * T_;
        float* o1 = o0 + (size_t)8 * T_;
#pragma unroll
        for (int nt = 0; nt < 8; nt++) {
            const int t = t0 + tg * 64 + nt * 8 + 2 * (lane & 3);
            float m0 = mask_at(mask, mk, b, t);
            float m1 = mask_at(mask, mk, b, t + 1);
            float2 v0, v1;
            v0.x = (acc[mf][nt][0] + bias0) * attn0[nt] * m0;
            v0.y = (acc[mf][nt][1] + bias0) * attn1[nt] * m1;
            v1.x = (acc[mf][nt][2] + bias1) * attn0[nt] * m0;
            v1.y = (acc[mf][nt][3] + bias1) * attn1[nt] * m1;
            *(float2*)(o0 + t) = v0;
            *(float2*)(o1 + t) = v1;
        }
    }
}

// ---------------------------------------------------------------------------
extern "C" void kernel_launch(void* const* d_in, const int* in_sizes, int n_in,
                              void* d_out, int out_size)
{
    const float* x     = (const float*)d_in[0];
    const float* guide = (const float*)d_in[1];
    const void*  mask  = (const void*)d_in[2];
    const float* gw    = (const float*)d_in[3];
    const float* gb    = (const float*)d_in[4];
    const float* abias = (const float*)d_in[5];
    const float* pw    = (const float*)d_in[6];
    const float* pb    = (const float*)d_in[7];
    float*       out   = (float*)d_out;

    static int attr_done = 0;
    if (!attr_done) {
        cudaFuncSetAttribute(conv_mma_kernel,
                             cudaFuncAttributeMaxDynamicSharedMemorySize, CONV_TILE_B);
        attr_done = 1;
    }

    prep1_kernel<<<P1_XT0 + 16384, 256>>>(x, pw);
    prep2_kernel<<<dim3(N_ / 8, B_), 256>>>(guide, gw, gb);
    prep3_kernel<<<1, 256>>>((const uint4*)mask, in_sizes[2] / 16);
    conv_mma_kernel<<<dim3(T_ / 128, COUT_ / 128, B_), 256, CONV_TILE_B>>>(pb, mask, abias, out);
}

// round 13
// speedup vs baseline: 6.2352x; 1.0649x over previous
#include <cuda_runtime.h>
#include <cuda_fp16.h>
#include <cstdint>

// Problem constants
#define B_    16
#define CIN_  256
#define T_    4096
#define N_    64
#define GC_   224
#define EC_   256
#define H_    8
#define HC_   32
#define COUT_ 256

// Scratch (no cudaMalloc allowed)
__device__ __half d_xt[(size_t)B_ * T_ * CIN_];       // x^T as fp16 [b][t][ci] (32 MB)
__device__ uint32_t d_wfrag[3 * 16 * 16 * 128];       // fp16x2 A-frags, conv
__device__ uint32_t d_gfrag[16 * 8 * 4 * 2 * 128];    // fp16x2 A-frags, attn
__device__ int    d_mask_kind;                        // 0=int32, 1=float32, 2=byte

// ---------------------------------------------------------------------------
// Helpers (base sm_100-legal: mma.sync sm_80+, ldmatrix sm_75+, cp.async sm_80+)
// ---------------------------------------------------------------------------
__device__ __forceinline__ uint32_t smem_u32(const void* p) {
    uint32_t a;
    asm("{ .reg .u64 t; cvta.to.shared.u64 t, %1; cvt.u32.u64 %0, t; }"
        : "=r"(a) : "l"(p));
    return a;
}
__device__ __forceinline__ uint32_t pack_h2(float lo, float hi) {
    __half2 h = __floats2half2_rn(lo, hi);   // .x = lo (lower 16 bits)
    return *(uint32_t*)&h;
}
__device__ __forceinline__ void ldsm_x2(uint32_t* r, uint32_t addr) {
    asm volatile("ldmatrix.sync.aligned.m8n8.x2.shared.b16 {%0, %1}, [%2];"
                 : "=r"(r[0]), "=r"(r[1]) : "r"(addr));
}
__device__ __forceinline__ void ldsm_x4(uint32_t* r, uint32_t addr) {
    asm volatile("ldmatrix.sync.aligned.m8n8.x4.shared.b16 {%0, %1, %2, %3}, [%4];"
                 : "=r"(r[0]), "=r"(r[1]), "=r"(r[2]), "=r"(r[3]) : "r"(addr));
}
__device__ __forceinline__ void mma_f16(float* d, const uint32_t* a, const uint32_t* b) {
    asm volatile(
        "mma.sync.aligned.m16n8k16.row.col.f32.f16.f16.f32 "
        "{%0,%1,%2,%3}, {%4,%5,%6,%7}, {%8,%9}, {%0,%1,%2,%3};"
        : "+f"(d[0]), "+f"(d[1]), "+f"(d[2]), "+f"(d[3])
        : "r"(a[0]), "r"(a[1]), "r"(a[2]), "r"(a[3]), "r"(b[0]), "r"(b[1]));
}
// cp.async 16B with zero-fill when invalid (src-size = 0)
__device__ __forceinline__ void cp16z(uint32_t dst, const void* src, bool valid) {
    int sz = valid ? 16 : 0;
    asm volatile("cp.async.cg.shared.global [%0], [%1], 16, %2;"
                 :: "r"(dst), "l"(src), "r"(sz) : "memory");
}
#define CP_COMMIT() asm volatile("cp.async.commit_group;" ::: "memory")
#define CP_WAIT(n)  asm volatile("cp.async.wait_group %0;" :: "n"(n) : "memory")

// Swizzled 512B-row tile (32 groups of 16B per row): logical group g stored at
// (g&24) | ((g&7) ^ (r&7)). Bank-group of g' depends only on g'&7, so
// ldmatrix's 8 rows at fixed g hit 8 distinct bank-groups.
__device__ __forceinline__ uint32_t swz512(int r, int g) {
    return (uint32_t)(r * 512 + (((g & 24) | ((g & 7) ^ (r & 7))) << 4));
}

__device__ __forceinline__ float mask_at(const void* mp, int kind, int b, int t)
{
    size_t idx = (size_t)b * T_ + t;
    if (kind == 0)      return ((const int*)mp)[idx]   != 0   ? 1.f : 0.f;
    else if (kind == 1) return ((const float*)mp)[idx] != 0.f ? 1.f : 0.f;
    else                return ((const unsigned char*)mp)[idx] ? 1.f : 0.f;
}

// ---------------------------------------------------------------------------
// Kernel P1: role-dispatched prep: wfrag pack (blocks 0..47) + xt (rest)
// ---------------------------------------------------------------------------
#define P1_XT0 48
__global__ __launch_bounds__(256) void prep1_kernel(
    const float* __restrict__ x, const float* __restrict__ pw)
{
    __shared__ float s[32][33];
    const int bid = blockIdx.x, tid = threadIdx.x;

    if (bid < 48) {
        // ---- wfrag pack (proven R10) ----
        const int cog = bid & 15, tap = bid >> 4;
        for (int i = tid; i < 512; i += 256) {
            int kc = i >> 5, lane = i & 31;
            int m = cog * 16 + (lane >> 2);
            int k = kc * 16 + (lane & 3) * 2;
            uint32_t* dst = &d_wfrag[((size_t)(tap * 16 + cog) * 16 + kc) * 128 + lane * 4];
            dst[0] = pack_h2(pw[(size_t)(m * 256 + k) * 3 + tap],
                             pw[(size_t)(m * 256 + k + 1) * 3 + tap]);
            dst[1] = pack_h2(pw[(size_t)((m + 8) * 256 + k) * 3 + tap],
                             pw[(size_t)((m + 8) * 256 + k + 1) * 3 + tap]);
            dst[2] = pack_h2(pw[(size_t)(m * 256 + k + 8) * 3 + tap],
                             pw[(size_t)(m * 256 + k + 9) * 3 + tap]);
            dst[3] = pack_h2(pw[(size_t)((m + 8) * 256 + k + 8) * 3 + tap],
                             pw[(size_t)((m + 8) * 256 + k + 9) * 3 + tap]);
        }
    } else {
        // ---- xt transpose + fp16 convert (proven R10) ----
        const int xb = bid - P1_XT0;           // 0 .. 16383
        const int b = xb >> 10;
        const int ci0 = ((xb & 1023) >> 7) * 32;
        const int t0 = ((xb & 127)) * 32;
        const int tx = tid & 31, ty = tid >> 5;
#pragma unroll
        for (int k = 0; k < 4; k++)
            s[ty + 8 * k][tx] = x[((size_t)(b * CIN_ + ci0 + ty + 8 * k)) * T_ + t0 + tx];
        __syncthreads();
#pragma unroll
        for (int k = 0; k < 4; k++)
            d_xt[((size_t)b * T_ + t0 + ty + 8 * k) * CIN_ + ci0 + tx] =
                __float2half_rn(s[tx][ty + 8 * k]);
    }
}

// ---------------------------------------------------------------------------
// Kernel P2: guide FC + fused gfrag packing (proven R11)
// ---------------------------------------------------------------------------
__global__ __launch_bounds__(256) void prep2_kernel(
    const float* __restrict__ guide, const float* __restrict__ gw,
    const float* __restrict__ gb)
{
    const int b  = blockIdx.y;
    const int n0 = blockIdx.x * 8;
    const int e  = threadIdx.x;

    __shared__ float s_guide[8 * GC_];
    __shared__ float s_gw[256 * 33];
    __shared__ float s_g[8][256];

    for (int i = threadIdx.x; i < 8 * GC_; i += 256) {
        int nn = i / GC_, k = i % GC_;
        s_guide[i] = guide[((size_t)(b * N_ + n0 + nn)) * GC_ + k];
    }

    float acc[8];
#pragma unroll
    for (int nn = 0; nn < 8; nn++) acc[nn] = 0.f;

    for (int k0 = 0; k0 < GC_; k0 += 32) {
        __syncthreads();
        for (int i = threadIdx.x; i < 256 * 32; i += 256) {
            int ee = i >> 5, j = i & 31;
            s_gw[ee * 33 + j] = gw[ee * GC_ + k0 + j];
        }
        __syncthreads();
#pragma unroll
        for (int j = 0; j < 32; j++) {
            float w = s_gw[e * 33 + j];
#pragma unroll
            for (int nn = 0; nn < 8; nn++)
                acc[nn] += s_guide[nn * GC_ + k0 + j] * w;
        }
    }

    const float bias = gb[e];
#pragma unroll
    for (int nn = 0; nn < 8; nn++) s_g[nn][e] = acc[nn] + bias;
    __syncthreads();

    const int mg = n0 >> 4;
    const int rbase = (n0 & 8) ? 1 : 0;      // regs {1,3} vs {0,2}
    for (int i = threadIdx.x; i < 512; i += 256) {
        int h = i >> 6, kc = (i >> 5) & 1, lane = i & 31;
        int nn = (lane >> 2);
        int ee = h * 32 + kc * 16 + (lane & 3) * 2;
        uint32_t* dst = &d_gfrag[(((size_t)(b * 8 + h) * 4 + mg) * 2 + kc) * 128 + lane * 4];
        dst[rbase]     = pack_h2(s_g[nn][ee],     s_g[nn][ee + 1]);
        dst[rbase + 2] = pack_h2(s_g[nn][ee + 8], s_g[nn][ee + 9]);
    }
}

// ---------------------------------------------------------------------------
// Kernel P3: mask classify (proven; tiny, keeps conv as launch #4 for ncu)
// ---------------------------------------------------------------------------
__global__ void prep3_kernel(const uint4* __restrict__ m16, int n16)
{
    __shared__ int s_c0, s_c23;
    if (threadIdx.x == 0) { s_c0 = 0; s_c23 = 0; }
    __syncthreads();
    int c0 = 0, c23 = 0;
    for (int i = threadIdx.x; i < n16; i += blockDim.x) {
        uint4 v = m16[i];
        uint32_t ws[4] = { v.x, v.y, v.z, v.w };
#pragma unroll
        for (int k = 0; k < 4; k++) {
            if (ws[k] & 0x000000FFu) c0++;
            if (ws[k] & 0xFFFF0000u) c23++;
        }
    }
    atomicAdd(&s_c0, c0);
    atomicAdd(&s_c23, c23);
    __syncthreads();
    if (threadIdx.x == 0) {
        int kind;
        if (s_c0 > 0 && s_c23 == 0) kind = 0;
        else if (s_c0 == 0 && s_c23 > 0) kind = 1;
        else kind = 2;
        d_mask_kind = kind;
    }
}

// ---------------------------------------------------------------------------
// Kernel C: fused conv1d(k=3) + max-sigmoid attention, fp16 m16n8k16.
// CTA = 128 co x 128 t. Tile: 130 rows (t0-1..t0+128) x 256 ci fp16, 512B
// swizzled rows, staged via cp.async in TWO K-halves (commit-groups) so
// compute on half A overlaps staging of half B. Mainloop per (kc16, nt):
// one ldmatrix.x4 (taps 0,1 x k-groups 0,1) + one ldmatrix.x2 (tap 2),
// addresses advanced incrementally (+4096/nt; swizzle XOR is nt-invariant).
// Attn sub-GEMM after the conv loop (tile resident); epilogue fused.
// ---------------------------------------------------------------------------
#define CONV_ROWS   130
#define CONV_TILE_B (CONV_ROWS * 512)   // 66560 B

__global__ __launch_bounds__(256, 2) void conv_mma_kernel(
    const float* __restrict__ pb, const void* __restrict__ mask,
    const float* __restrict__ abias, float* __restrict__ out)
{
    extern __shared__ __align__(16) char s_dyn[];
    const int b = blockIdx.z, co0 = blockIdx.y * 128, t0 = blockIdx.x * 128;
    const int tid = threadIdx.x, w = tid >> 5, lane = tid & 31;
    const int cog = w & 3, tg = w >> 2;
    const int hw = blockIdx.y * 4 + cog;     // this warp's head
    const uint32_t smb = smem_u32(s_dyn);
    const __half* xtb = d_xt + (size_t)b * T_ * CIN_;

    // ---- stage half A (ci 0..127, groups 0..15) ----
#pragma unroll
    for (int it = 0; it < 9; it++) {
        int idx = tid + it * 256;            // 2080 x 16B
        if (it < 8 || idx < 2080) {
            int r = idx >> 4, g = idx & 15;
            int gt = t0 - 1 + r;
            int gtc = gt < 0 ? 0 : (gt >= T_ ? T_ - 1 : gt);
            cp16z(smb + swz512(r, g), xtb + (size_t)gtc * 256 + g * 8,
                  gt >= 0 && gt < T_);
        }
    }
    CP_COMMIT();
    // ---- stage half B (ci 128..255, groups 16..31) ----
#pragma unroll
    for (int it = 0; it < 9; it++) {
        int idx = tid + it * 256;
        if (it < 8 || idx < 2080) {
            int r = idx >> 4, g = 16 + (idx & 15);
            int gt = t0 - 1 + r;
            int gtc = gt < 0 ? 0 : (gt >= T_ ? T_ - 1 : gt);
            cp16z(smb + swz512(r, g), xtb + (size_t)gtc * 256 + g * 8,
                  gt >= 0 && gt < T_);
        }
    }
    CP_COMMIT();

    float acc[2][8][4];
#pragma unroll
    for (int mf = 0; mf < 2; mf++)
#pragma unroll
        for (int nt = 0; nt < 8; nt++)
#pragma unroll
            for (int r = 0; r < 4; r++) acc[mf][nt][r] = 0.f;

    const int lane7 = lane & 7;
    const int k_q   = (lane >> 3) & 1;   // x4: q&1 (k-group); also x2 matrix sel
    const int s_q   = (lane >> 4) & 1;   // x4: q>>1 (tap 0/1)

    // ---- compute: two K-halves, pipelined against staging ----
#pragma unroll
    for (int half = 0; half < 2; half++) {
        if (half == 0) { CP_WAIT(1); } else { CP_WAIT(0); }
        __syncthreads();
#pragma unroll 4
        for (int kcl = 0; kcl < 8; kcl++) {
            const int kc16 = half * 8 + kcl;
            uint32_t afr[2][3][4];
#pragma unroll
            for (int mf = 0; mf < 2; mf++) {
                const int cog16 = blockIdx.y * 8 + cog * 2 + mf;
#pragma unroll
                for (int tap = 0; tap < 3; tap++) {
                    const uint4 v = *(const uint4*)&d_wfrag[((size_t)(tap * 16 + cog16) * 16 + kc16) * 128 + lane * 4];
                    afr[mf][tap][0] = v.x; afr[mf][tap][1] = v.y;
                    afr[mf][tap][2] = v.z; afr[mf][tap][3] = v.w;
                }
            }
            // Incremental ldsm addresses: swizzle XOR is nt-invariant.
            uint32_t a4 = smb + swz512(tg * 64 + s_q + lane7, kc16 * 2 + k_q);
            uint32_t a2 = smb + swz512(tg * 64 + 2 + lane7,   kc16 * 2 + k_q);
#pragma unroll
            for (int nt = 0; nt < 8; nt++) {
                uint32_t q0[4], q1[2];
                ldsm_x4(q0, a4);             // {tap0 k0, tap0 k1, tap1 k0, tap1 k1}
                ldsm_x2(q1, a2);             // {tap2 k0, tap2 k1}
                a4 += 4096; a2 += 4096;
#pragma unroll
                for (int mf = 0; mf < 2; mf++) {
                    mma_f16(acc[mf][nt], afr[mf][0], q0);
                    mma_f16(acc[mf][nt], afr[mf][1], q0 + 2);
                    mma_f16(acc[mf][nt], afr[mf][2], q1);
                }
            }
        }
    }

    // ---- attention for this warp's head (tile fully resident) ----
    float attn0[8], attn1[8];
    {
        const float ab = abias[hw];
#pragma unroll
        for (int nt = 0; nt < 8; nt++) {
            float a4v[4][4];
#pragma unroll
            for (int mg = 0; mg < 4; mg++)
#pragma unroll
                for (int r = 0; r < 4; r++) a4v[mg][r] = 0.f;
#pragma unroll
            for (int kca = 0; kca < 2; kca++) {
                const int kc16 = hw * 2 + kca;
                const int gk = kc16 * 2 + k_q;
                const int r = 1 + tg * 64 + nt * 8 + lane7;
                uint32_t bfr[2];
                ldsm_x2(bfr, smb + swz512(r, gk));
#pragma unroll
                for (int mg = 0; mg < 4; mg++) {
                    const uint4 v = *(const uint4*)&d_gfrag[(((size_t)(b * 8 + hw) * 4 + mg) * 2 + kca) * 128 + lane * 4];
                    uint32_t gfr[4] = { v.x, v.y, v.z, v.w };
                    mma_f16(a4v[mg], gfr, bfr);
                }
            }
            float m0 = -1e30f, m1 = -1e30f;
#pragma unroll
            for (int mg = 0; mg < 4; mg++) {
                m0 = fmaxf(m0, fmaxf(a4v[mg][0], a4v[mg][2]));
                m1 = fmaxf(m1, fmaxf(a4v[mg][1], a4v[mg][3]));
            }
#pragma unroll
            for (int d = 4; d <= 16; d <<= 1) {
                m0 = fmaxf(m0, __shfl_xor_sync(0xffffffffu, m0, d));
                m1 = fmaxf(m1, __shfl_xor_sync(0xffffffffu, m1, d));
            }
            float z0 = m0 * 0.17677669529663687f + ab;
            float z1 = m1 * 0.17677669529663687f + ab;
            attn0[nt] = 1.f / (1.f + __expf(-z0));
            attn1[nt] = 1.f / (1.f + __expf(-z1));
        }
    }

    // ---- epilogue: (+pb) * attn * mask ----
    const int mk = d_mask_kind;
#pragma unroll
    for (int mf = 0; mf < 2; mf++) {
        const int cob = co0 + cog * 32 + mf * 16 + (lane >> 2);
        const float bias0 = pb[cob], bias1 = pb[cob + 8];
        float* o0 = out + ((size_t)(b * 256 + cob)) * T_;
        float* o1 = o0 + (size_t)8 * T_;
#pragma unroll
        for (int nt = 0; nt < 8; nt++) {
            const int t = t0 + tg * 64 + nt * 8 + 2 * (lane & 3);
            float m0 = mask_at(mask, mk, b, t);
            float m1 = mask_at(mask, mk, b, t + 1);
            float2 v0, v1;
            v0.x = (acc[mf][nt][0] + bias0) * attn0[nt] * m0;
            v0.y = (acc[mf][nt][1] + bias0) * attn1[nt] * m1;
            v1.x = (acc[mf][nt][2] + bias1) * attn0[nt] * m0;
            v1.y = (acc[mf][nt][3] + bias1) * attn1[nt] * m1;
            *(float2*)(o0 + t) = v0;
            *(float2*)(o1 + t) = v1;
        }
    }
}

// ---------------------------------------------------------------------------
extern "C" void kernel_launch(void* const* d_in, const int* in_sizes, int n_in,
                              void* d_out, int out_size)
{
    const float* x     = (const float*)d_in[0];
    const float* guide = (const float*)d_in[1];
    const void*  mask  = (const void*)d_in[2];
    const float* gw    = (const float*)d_in[3];
    const float* gb    = (const float*)d_in[4];
    const float* abias = (const float*)d_in[5];
    const float* pw    = (const float*)d_in[6];
    const float* pb    = (const float*)d_in[7];
    float*       out   = (float*)d_out;

    static int attr_done = 0;
    if (!attr_done) {
        cudaFuncSetAttribute(conv_mma_kernel,
                             cudaFuncAttributeMaxDynamicSharedMemorySize, CONV_TILE_B);
        attr_done = 1;
    }

    prep1_kernel<<<P1_XT0 + 16384, 256>>>(x, pw);
    prep2_kernel<<<dim3(N_ / 8, B_), 256>>>(guide, gw, gb);
    prep3_kernel<<<1, 256>>>((const uint4*)mask, in_sizes[2] / 16);
    conv_mma_kernel<<<dim3(T_ / 128, COUT_ / 128, B_), 256, CONV_TILE_B>>>(pb, mask, abias, out);
}